// round 11
// baseline (speedup 1.0000x reference)
#include <cuda_runtime.h>
#include <cuda_fp16.h>
#include <math.h>
#include <stdint.h>

#define LN_ 12
#define HN_ 12
#define DM_ 768
#define TM_ 1024
#define BN_ 4
#define VN_ 50257
#define DH_ 64
#define MR_ (BN_*TM_)
#define FF_ (4*DM_)
#define QS_ (3*DM_)
#define DD_ (DM_*DM_)

// ---------------- scratch ----------------
__device__ float g_x  [MR_*DM_];
__device__ float g_bqkv[LN_*QS_];
__device__ __half g_qkv[MR_*QS_];
__device__ __half g_h[MR_*DM_];
__device__ __half g_y[MR_*DM_];
__device__ __half g_f[MR_*FF_];
__device__ __half g_Wqkv[LN_*3*DD_];
__device__ __half g_Wo[LN_*DD_];
__device__ __half g_Wf[LN_*DM_*FF_];
__device__ __half g_Wp[LN_*DM_*FF_];
__device__ __half g_Wlm[(size_t)VN_*DM_];

// ---------------- PTX helpers (base sm_103 target only!) ----------------
__device__ __forceinline__ uint32_t su32(const void* p){
    uint32_t a; asm("{ .reg .u64 t; cvta.to.shared.u64 t, %1; cvt.u32.u64 %0, t; }":"=r"(a):"l"(p)); return a;
}
__device__ __forceinline__ void mma16816(float* c, const uint32_t* a, const uint32_t* b){
    asm volatile("mma.sync.aligned.m16n8k16.row.col.f32.f16.f16.f32 "
        "{%0,%1,%2,%3},{%4,%5,%6,%7},{%8,%9},{%0,%1,%2,%3};"
        : "+f"(c[0]),"+f"(c[1]),"+f"(c[2]),"+f"(c[3])
        : "r"(a[0]),"r"(a[1]),"r"(a[2]),"r"(a[3]),"r"(b[0]),"r"(b[1]));
}
__device__ __forceinline__ void ldsm4(uint32_t* r, uint32_t a){
    asm volatile("ldmatrix.sync.aligned.m8n8.x4.shared.b16 {%0,%1,%2,%3},[%4];"
        :"=r"(r[0]),"=r"(r[1]),"=r"(r[2]),"=r"(r[3]):"r"(a));
}
__device__ __forceinline__ void ldsm4t(uint32_t* r, uint32_t a){
    asm volatile("ldmatrix.sync.aligned.m8n8.x4.trans.shared.b16 {%0,%1,%2,%3},[%4];"
        :"=r"(r[0]),"=r"(r[1]),"=r"(r[2]),"=r"(r[3]):"r"(a));
}
__device__ __forceinline__ void cpa(uint32_t d, const void* g, int vb){
    asm volatile("cp.async.cg.shared.global [%0],[%1],16,%2;"::"r"(d),"l"(g),"r"(vb):"memory");
}
__device__ __forceinline__ void cpcommit(){ asm volatile("cp.async.commit_group;":::"memory"); }
template<int N> __device__ __forceinline__ void cpwait(){ asm volatile("cp.async.wait_group %0;"::"n"(N):"memory"); }

// ---------------- weight transpose + fp16 convert: W[K,N] tile -> o[N,K] ----------------
__device__ __forceinline__ void wtile(const float* __restrict__ W, __half* __restrict__ o, int K, int N){
    __shared__ float t[32][33];
    int k0 = blockIdx.y*32, n0 = blockIdx.x*32;
    #pragma unroll
    for (int i=0;i<4;i++){
        int k = k0 + threadIdx.y + i*8, n = n0 + threadIdx.x;
        t[threadIdx.y+i*8][threadIdx.x] = (n<N) ? W[(size_t)k*N+n] : 0.f;
    }
    __syncthreads();
    #pragma unroll
    for (int i=0;i<4;i++){
        int n = n0 + threadIdx.y + i*8, k = k0 + threadIdx.x;
        if (n<N) o[(size_t)n*K+k] = __float2half(t[threadIdx.x][threadIdx.y+i*8]);
    }
}

__global__ void wconvA(const float* __restrict__ Wq, const float* __restrict__ Wk,
                       const float* __restrict__ Wv, const float* __restrict__ Wo4,
                       __half* __restrict__ wqkv, __half* __restrict__ wo){
    int l = blockIdx.z >> 2, which = blockIdx.z & 3;
    const float* src = which==0?Wq:which==1?Wk:which==2?Wv:Wo4;
    src += (size_t)l*DD_;
    __half* dst = (which<3) ? wqkv + (size_t)l*3*DD_ + (size_t)which*DD_
                            : wo   + (size_t)l*DD_;
    wtile(src, dst, DM_, DM_);
}
__global__ void wconvB(const float* __restrict__ Wfc, const float* __restrict__ Wpr,
                       __half* __restrict__ wf, __half* __restrict__ wp){
    int l = blockIdx.z >> 1;
    if ((blockIdx.z & 1)==0){
        if (blockIdx.x>=96 || blockIdx.y>=24) return;
        wtile(Wfc + (size_t)l*DM_*FF_, wf + (size_t)l*DM_*FF_, DM_, FF_);
    } else {
        if (blockIdx.x>=24 || blockIdx.y>=96) return;
        wtile(Wpr + (size_t)l*DM_*FF_, wp + (size_t)l*DM_*FF_, FF_, DM_);
    }
}
__global__ void wconvLM(const float* __restrict__ Wlm, __half* __restrict__ wlm){
    wtile(Wlm, wlm, DM_, VN_);
}

// ---------------- embedding + bias concat ----------------
__global__ void embed_kernel(const int* __restrict__ idx, const float* __restrict__ wte,
                             const float* __restrict__ wpe, float* __restrict__ x,
                             const float* __restrict__ bq, const float* __restrict__ bk,
                             const float* __restrict__ bv, float* __restrict__ bqkv){
    int row = blockIdx.x;
    float4 a = ((const float4*)(wte + (size_t)idx[row]*DM_))[threadIdx.x];
    float4 p = ((const float4*)(wpe + (size_t)(row&(TM_-1))*DM_))[threadIdx.x];
    a.x+=p.x; a.y+=p.y; a.z+=p.z; a.w+=p.w;
    ((float4*)(x + (size_t)row*DM_))[threadIdx.x] = a;
    if (row < LN_){
        for (int j=threadIdx.x; j<QS_; j+=192){
            float v = (j<DM_) ? bq[row*DM_+j] : (j<2*DM_) ? bk[row*DM_+j-DM_] : bv[row*DM_+j-2*DM_];
            bqkv[row*QS_+j] = v;
        }
    }
}

// ---------------- layernorm -> fp16 (192 threads) ----------------
__global__ void ln_kernel(const float* __restrict__ x, const float* __restrict__ w, const float* __restrict__ b,
                          __half* __restrict__ oh){
    int row = blockIdx.x, tid = threadIdx.x;
    float4 v = ((const float4*)(x + (size_t)row*DM_))[tid];
    float s = v.x+v.y+v.z+v.w;
    float sq = v.x*v.x+v.y*v.y+v.z*v.z+v.w*v.w;
    __shared__ float ss[6], sp[6];
    #pragma unroll
    for (int o=16;o;o>>=1){ s+=__shfl_xor_sync(~0u,s,o); sq+=__shfl_xor_sync(~0u,sq,o); }
    if ((tid&31)==0){ ss[tid>>5]=s; sp[tid>>5]=sq; }
    __syncthreads();
    s=0; sq=0;
    #pragma unroll
    for (int i=0;i<6;i++){ s+=ss[i]; sq+=sp[i]; }
    float mean = s*(1.f/DM_), var = sq*(1.f/DM_)-mean*mean, rstd = rsqrtf(var+1e-5f);
    float4 wv = ((const float4*)w)[tid], bv = ((const float4*)b)[tid];
    __half hh[4];
    hh[0] = __float2half((v.x-mean)*rstd*wv.x+bv.x);
    hh[1] = __float2half((v.y-mean)*rstd*wv.y+bv.y);
    hh[2] = __float2half((v.z-mean)*rstd*wv.z+bv.z);
    hh[3] = __float2half((v.w-mean)*rstd*wv.w+bv.w);
    ((uint2*)(oh + (size_t)row*DM_))[tid] = *(uint2*)hh;
}

// ---------------- narrow GEMM (wo/pr): CTA 128x128x64, 2 CTAs/SM, EPI: bias+res->f32 ----------------
#define STGB   36864u
#define BT_    18432u
#define TGSMEM (2*36864)
__global__ void __launch_bounds__(256,2)
tgemm_res(const __half* __restrict__ A, const __half* __restrict__ B,
          const float* __restrict__ bias, const float* __restrict__ res,
          float* __restrict__ outf, int N, int K){
    extern __shared__ char smem[];
    uint32_t sb = su32(smem);
    const int tid = threadIdx.x;
    const int m0 = blockIdx.x*128, n0 = blockIdx.y*128;
    const int NT = K >> 6;

    auto load_tile = [&](int kt){
        uint32_t base = sb + (uint32_t)(kt&1)*STGB;
        #pragma unroll
        for (int i=0;i<4;i++){
            int id = tid + i*256; int r = id>>3, c = id&7;
            cpa(base + (uint32_t)(r*144 + c*16),
                (const char*)(A + (size_t)(m0+r)*K + kt*64) + c*16, 16);
        }
        #pragma unroll
        for (int i=0;i<4;i++){
            int id = tid + i*256; int r = id>>3, c = id&7;
            cpa(base + BT_ + (uint32_t)(r*144 + c*16),
                (const char*)(B + (size_t)(n0+r)*K + kt*64) + c*16, 16);
        }
        cpcommit();
    };

    load_tile(0); if (NT>1) load_tile(1);

    const int l = tid & 31;
    const int wid = tid >> 5, wm = wid & 1, wn = wid >> 1;
    const uint32_t aoff = (uint32_t)((wm*64 + (l&7) + ((l>>3)&1)*8)*144 + (l>>4)*16);
    const uint32_t boff = (uint32_t)((wn*32 + (l&7) + (l>>4)*8)*144 + ((l>>3)&1)*16);

    float acc[4][4][4];
    #pragma unroll
    for (int i=0;i<4;i++) for (int j=0;j<4;j++) for (int r=0;r<4;r++) acc[i][j][r]=0.f;

    for (int kt=0; kt<NT; kt++){
        if (kt+2<=NT) cpwait<1>();
        else cpwait<0>();
        __syncthreads();
        uint32_t base = sb + (uint32_t)(kt&1)*STGB;
        #pragma unroll
        for (int ks=0; ks<4; ks++){
            uint32_t af[4][4], bf_[2][4];
            #pragma unroll
            for (int mi=0; mi<4; mi++)
                ldsm4(af[mi], base + aoff + (uint32_t)(mi*16*144 + ks*32));
            #pragma unroll
            for (int nb=0; nb<2; nb++)
                ldsm4(bf_[nb], base + BT_ + boff + (uint32_t)(nb*16*144 + ks*32));
            #pragma unroll
            for (int mi=0; mi<4; mi++)
                #pragma unroll
                for (int ni=0; ni<4; ni++)
                    mma16816(acc[mi][ni], af[mi], &bf_[ni>>1][(ni&1)*2]);
        }
        __syncthreads();
        if (kt+2<NT) load_tile(kt+2);
    }

    #pragma unroll
    for (int mi=0; mi<4; mi++){
        #pragma unroll
        for (int ni=0; ni<4; ni++){
            #pragma unroll
            for (int half_=0; half_<2; half_++){
                int r = m0 + wm*64 + mi*16 + (l>>2) + half_*8;
                int c = n0 + wn*32 + ni*8 + (l&3)*2;
                size_t o = (size_t)r*N + c;
                outf[o]   = acc[mi][ni][half_*2]   + bias[c]   + res[o];
                outf[o+1] = acc[mi][ni][half_*2+1] + bias[c+1] + res[o+1];
            }
        }
    }
}

// ---------------- wide GEMM (qkv/fc/lm): CTA 128x256x64, 1 CTA/SM, warp 64x64 ----------------
// EPI: 0 bias->fp16, 2 bias+gelu->fp16, 3 none->f32
#define W_STG  55296u          // (128+256)*144
#define W_BT   18432u          // 128*144
#define WSMEM  (2*55296)
template<int EPI>
__global__ void __launch_bounds__(256,1)
tgemmW(const __half* __restrict__ A, const __half* __restrict__ B,
       const float* __restrict__ bias,
       float* __restrict__ outf, __half* __restrict__ outh,
       int N, int K){
    extern __shared__ char smem[];
    uint32_t sb = su32(smem);
    const int tid = threadIdx.x;
    const int m0 = blockIdx.x*128, n0 = blockIdx.y*256;
    const int NT = K >> 6;

    auto load_tile = [&](int kt){
        uint32_t base = sb + (uint32_t)(kt&1)*W_STG;
        #pragma unroll
        for (int i=0;i<4;i++){
            int id = tid + i*256; int r = id>>3, c = id&7;
            cpa(base + (uint32_t)(r*144 + c*16),
                (const char*)(A + (size_t)(m0+r)*K + kt*64) + c*16, 16);
        }
        #pragma unroll
        for (int i=0;i<8;i++){
            int id = tid + i*256; int r = id>>3, c = id&7;
            int vb = (n0+r) < N ? 16 : 0;
            cpa(base + W_BT + (uint32_t)(r*144 + c*16),
                (const char*)(B + (size_t)(n0+r)*K + kt*64) + c*16, vb);
        }
        cpcommit();
    };

    load_tile(0); if (NT>1) load_tile(1);

    const int l = tid & 31;
    const int wid = tid >> 5, wm = wid & 1, wn = wid >> 1;
    const uint32_t aoff = (uint32_t)((wm*64 + (l&7) + ((l>>3)&1)*8)*144 + (l>>4)*16);
    const uint32_t boff = (uint32_t)((wn*64 + (l&7) + (l>>4)*8)*144 + ((l>>3)&1)*16);

    float acc[4][8][4];
    #pragma unroll
    for (int i=0;i<4;i++) for (int j=0;j<8;j++) for (int r=0;r<4;r++) acc[i][j][r]=0.f;

    for (int kt=0; kt<NT; kt++){
        if (kt+2<=NT) cpwait<1>();
        else cpwait<0>();
        __syncthreads();
        uint32_t base = sb + (uint32_t)(kt&1)*W_STG;
        #pragma unroll
        for (int ks=0; ks<4; ks++){
            uint32_t af[4][4], bf_[4][4];
            #pragma unroll
            for (int mi=0; mi<4; mi++)
                ldsm4(af[mi], base + aoff + (uint32_t)(mi*16*144 + ks*32));
            #pragma unroll
            for (int nb=0; nb<4; nb++)
                ldsm4(bf_[nb], base + W_BT + boff + (uint32_t)(nb*16*144 + ks*32));
            #pragma unroll
            for (int mi=0; mi<4; mi++)
                #pragma unroll
                for (int ni=0; ni<8; ni++)
                    mma16816(acc[mi][ni], af[mi], &bf_[ni>>1][(ni&1)*2]);
        }
        __syncthreads();
        if (kt+2<NT) load_tile(kt+2);
    }

    const float kg = 0.7978845608028654f;
    #pragma unroll
    for (int mi=0; mi<4; mi++){
        #pragma unroll
        for (int ni=0; ni<8; ni++){
            #pragma unroll
            for (int half_=0; half_<2; half_++){
                int r = m0 + wm*64 + mi*16 + (l>>2) + half_*8;
                int c = n0 + wn*64 + ni*8 + (l&3)*2;
                float v0 = acc[mi][ni][half_*2], v1 = acc[mi][ni][half_*2+1];
                #pragma unroll
                for (int e=0; e<2; e++){
                    int cc = c + e;
                    if (cc < N){
                        float v = e ? v1 : v0;
                        size_t o = (size_t)r*N + cc;
                        if (EPI==0) outh[o] = __float2half(v + bias[cc]);
                        else if (EPI==2){
                            v += bias[cc];
                            float u = kg*(v + 0.044715f*v*v*v);
                            v = 0.5f*v*(1.f + tanhf(u));
                            outh[o] = __float2half(v);
                        } else outf[o] = v;
                    }
                }
            }
        }
    }
}

// ---------------- tensor-core flash attention (fp16 QK + PV, fp32 softmax) ----------------
__global__ void __launch_bounds__(128)
attn_kernel(const __half* __restrict__ qkv, __half* __restrict__ y){
    __shared__ __half Qs[64*72], Ks[64*72], Vs[64*72];
    const int tid = threadIdx.x, l = tid & 31, w = tid >> 5;
    const int qb = blockIdx.x, h = blockIdx.y, b = blockIdx.z;
    const __half* qp = qkv + (size_t)(b*TM_ + qb*64)*QS_ + h*DH_;
    const __half* kp = qkv + (size_t)b*TM_*QS_ + DM_   + h*DH_;
    const __half* vp = qkv + (size_t)b*TM_*QS_ + 2*DM_ + h*DH_;
    uint32_t sQ = su32(Qs), sK = su32(Ks), sV = su32(Vs);

    #pragma unroll
    for (int i=0;i<4;i++){
        int id = tid + i*128; int r = id>>3, c = id&7;
        *(uint4*)(Qs + r*72 + c*8) = *(const uint4*)(qp + (size_t)r*QS_ + c*8);
    }
    __syncthreads();
    uint32_t aq[4][4];
    const uint32_t aoff = (uint32_t)((w*16 + (l&7) + ((l>>3)&1)*8)*144 + (l>>4)*16);
    #pragma unroll
    for (int ks=0;ks<4;ks++) ldsm4(aq[ks], sQ + aoff + ks*32);

    float O[8][4];
    #pragma unroll
    for (int j=0;j<8;j++) for (int e=0;e<4;e++) O[j][e]=0.f;
    float m0=-1e30f, m1=-1e30f, l0=0.f, l1=0.f;
    const int row0 = qb*64 + w*16 + (l>>2);

    for (int kt=0; kt<=qb; kt++){
        __syncthreads();
        #pragma unroll
        for (int i=0;i<4;i++){
            int id = tid + i*128; int r = id>>3, c = id&7;
            *(uint4*)(Ks + r*72 + c*8) = *(const uint4*)(kp + (size_t)(kt*64+r)*QS_ + c*8);
            *(uint4*)(Vs + r*72 + c*8) = *(const uint4*)(vp + (size_t)(kt*64+r)*QS_ + c*8);
        }
        __syncthreads();

        float sc[8][4];
        #pragma unroll
        for (int j=0;j<8;j++) for (int e=0;e<4;e++) sc[j][e]=0.f;
        const uint32_t boffK = (uint32_t)(((l&7) + (l>>4)*8)*144 + ((l>>3)&1)*16);
        #pragma unroll
        for (int ks=0;ks<4;ks++){
            #pragma unroll
            for (int nb=0;nb<4;nb++){
                uint32_t bk[4];
                ldsm4(bk, sK + boffK + (uint32_t)(nb*16*144 + ks*32));
                mma16816(sc[nb*2],   aq[ks], bk);
                mma16816(sc[nb*2+1], aq[ks], bk+2);
            }
        }
        #pragma unroll
        for (int j=0;j<8;j++){
            #pragma unroll
            for (int e=0;e<4;e++) sc[j][e] *= 0.125f;
        }
        if (kt==qb){
            #pragma unroll
            for (int j=0;j<8;j++){
                int col = kt*64 + j*8 + (l&3)*2;
                if (col   > row0)   sc[j][0] = -1e30f;
                if (col+1 > row0)   sc[j][1] = -1e30f;
                if (col   > row0+8) sc[j][2] = -1e30f;
                if (col+1 > row0+8) sc[j][3] = -1e30f;
            }
        }
        float mx0=-1e30f, mx1=-1e30f;
        #pragma unroll
        for (int j=0;j<8;j++){
            mx0 = fmaxf(mx0, fmaxf(sc[j][0], sc[j][1]));
            mx1 = fmaxf(mx1, fmaxf(sc[j][2], sc[j][3]));
        }
        mx0 = fmaxf(mx0, __shfl_xor_sync(~0u, mx0, 1));
        mx0 = fmaxf(mx0, __shfl_xor_sync(~0u, mx0, 2));
        mx1 = fmaxf(mx1, __shfl_xor_sync(~0u, mx1, 1));
        mx1 = fmaxf(mx1, __shfl_xor_sync(~0u, mx1, 2));
        float nm0 = fmaxf(m0, mx0), nm1 = fmaxf(m1, mx1);
        float f0 = __expf(m0-nm0), f1 = __expf(m1-nm1);
        float s0 = 0.f, s1 = 0.f;
        uint32_t ap[4][4];
        #pragma unroll
        for (int j2=0;j2<4;j2++){
            float p00=__expf(sc[2*j2][0]-nm0),   p01=__expf(sc[2*j2][1]-nm0);
            float p02=__expf(sc[2*j2][2]-nm1),   p03=__expf(sc[2*j2][3]-nm1);
            float p10=__expf(sc[2*j2+1][0]-nm0), p11=__expf(sc[2*j2+1][1]-nm0);
            float p12=__expf(sc[2*j2+1][2]-nm1), p13=__expf(sc[2*j2+1][3]-nm1);
            s0 += p00+p01+p10+p11;
            s1 += p02+p03+p12+p13;
            __half2 h0 = __floats2half2_rn(p00,p01), h1 = __floats2half2_rn(p02,p03);
            __half2 h2v = __floats2half2_rn(p10,p11), h3 = __floats2half2_rn(p12,p13);
            ap[j2][0] = *(uint32_t*)&h0;  ap[j2][1] = *(uint32_t*)&h1;
            ap[j2][2] = *(uint32_t*)&h2v; ap[j2][3] = *(uint32_t*)&h3;
        }
        s0 += __shfl_xor_sync(~0u, s0, 1); s0 += __shfl_xor_sync(~0u, s0, 2);
        s1 += __shfl_xor_sync(~0u, s1, 1); s1 += __shfl_xor_sync(~0u, s1, 2);
        l0 = l0*f0 + s0; l1 = l1*f1 + s1; m0 = nm0; m1 = nm1;
        #pragma unroll
        for (int j=0;j<8;j++){ O[j][0]*=f0; O[j][1]*=f0; O[j][2]*=f1; O[j][3]*=f1; }
        #pragma unroll
        for (int kp2=0;kp2<4;kp2++){
            #pragma unroll
            for (int dv=0;dv<4;dv++){
                uint32_t bv[4];
                ldsm4t(bv, sV + (uint32_t)((kp2*16 + (l&7) + ((l>>3)&1)*8)*144 + dv*32 + (l>>4)*16));
                mma16816(O[dv*2],   ap[kp2], bv);
                mma16816(O[dv*2+1], ap[kp2], bv+2);
            }
        }
    }
    float inv0 = 1.f/l0, inv1 = 1.f/l1;
    size_t r0 = (size_t)(b*TM_ + qb*64 + w*16 + (l>>2));
    #pragma unroll
    for (int j=0;j<8;j++){
        int d = h*DH_ + j*8 + (l&3)*2;
        __half2 o0 = __floats2half2_rn(O[j][0]*inv0, O[j][1]*inv0);
        __half2 o1 = __floats2half2_rn(O[j][2]*inv1, O[j][3]*inv1);
        *(__half2*)(y + r0*DM_ + d)     = o0;
        *(__half2*)(y + (r0+8)*DM_ + d) = o1;
    }
}

// ---------------- launch ----------------
extern "C" void kernel_launch(void* const* d_in, const int* in_sizes, int n_in,
                              void* d_out, int out_size){
    const int*   idx  = (const int*)  d_in[0];
    const float* wte  = (const float*)d_in[1];
    const float* wpe  = (const float*)d_in[2];
    const float* ln1w = (const float*)d_in[3];
    const float* ln1b = (const float*)d_in[4];
    const float* Wq   = (const float*)d_in[5];
    const float* bq   = (const float*)d_in[6];
    const float* Wk   = (const float*)d_in[7];
    const float* bk   = (const float*)d_in[8];
    const float* Wv   = (const float*)d_in[9];
    const float* bv   = (const float*)d_in[10];
    const float* Wo   = (const float*)d_in[11];
    const float* bo   = (const float*)d_in[12];
    const float* ln2w = (const float*)d_in[13];
    const float* ln2b = (const float*)d_in[14];
    const float* Wfc  = (const float*)d_in[15];
    const float* bfc  = (const float*)d_in[16];
    const float* Wpr  = (const float*)d_in[17];
    const float* bpr  = (const float*)d_in[18];
    const float* lnfw = (const float*)d_in[19];
    const float* lnfb = (const float*)d_in[20];
    const float* Wlm  = (const float*)d_in[21];
    float* out = (float*)d_out;

    float *x,*bqkv;
    __half *qkv,*h,*y,*f,*wqkv,*wo,*wf,*wp,*wlm;
    cudaGetSymbolAddress((void**)&x, g_x);
    cudaGetSymbolAddress((void**)&bqkv, g_bqkv);
    cudaGetSymbolAddress((void**)&qkv, g_qkv);
    cudaGetSymbolAddress((void**)&h, g_h);
    cudaGetSymbolAddress((void**)&y, g_y);
    cudaGetSymbolAddress((void**)&f, g_f);
    cudaGetSymbolAddress((void**)&wqkv, g_Wqkv);
    cudaGetSymbolAddress((void**)&wo, g_Wo);
    cudaGetSymbolAddress((void**)&wf, g_Wf);
    cudaGetSymbolAddress((void**)&wp, g_Wp);
    cudaGetSymbolAddress((void**)&wlm, g_Wlm);

    cudaFuncSetAttribute(tgemm_res, cudaFuncAttributeMaxDynamicSharedMemorySize, TGSMEM);
    cudaFuncSetAttribute(tgemmW<0>, cudaFuncAttributeMaxDynamicSharedMemorySize, WSMEM);
    cudaFuncSetAttribute(tgemmW<2>, cudaFuncAttributeMaxDynamicSharedMemorySize, WSMEM);
    cudaFuncSetAttribute(tgemmW<3>, cudaFuncAttributeMaxDynamicSharedMemorySize, WSMEM);

    // order tuned so the ncu capture slot lands on tgemmW<0> (the qkv GEMM)
    embed_kernel<<<MR_, 192>>>(idx, wte, wpe, x, bq, bk, bv, bqkv);
    wconvA<<<dim3(24,24,4*LN_), dim3(32,8)>>>(Wq, Wk, Wv, Wo, wqkv, wo);
    ln_kernel<<<MR_,192>>>(x, ln1w, ln1b, h);
    dim3 gqkv(32, QS_/256), g768(32, 6), g3072(32, FF_/256), glm(32, (VN_+255)/256);
    tgemmW<0><<<gqkv,256,WSMEM>>>(h, wqkv, bqkv, nullptr, qkv, QS_, DM_);   // layer 0 qkv
    wconvB<<<dim3(96,96,2*LN_), dim3(32,8)>>>(Wfc, Wpr, wf, wp);
    wconvLM<<<dim3((VN_+31)/32, 24), dim3(32,8)>>>(Wlm, wlm);

    for (int l=0; l<LN_; l++){
        size_t wdd = (size_t)l*DD_, wq3 = (size_t)l*3*DD_, wff = (size_t)l*DM_*FF_;
        if (l > 0){
            ln_kernel<<<MR_,192>>>(x, ln1w+l*DM_, ln1b+l*DM_, h);
            tgemmW<0><<<gqkv,256,WSMEM>>>(h, wqkv+wq3, bqkv+l*QS_, nullptr, qkv, QS_, DM_);
        }
        attn_kernel<<<dim3(16,HN_,BN_),128>>>(qkv, y);
        tgemm_res<<<g768,256,TGSMEM>>>(y, wo+wdd, bo+l*DM_, x, x, DM_, DM_);
        ln_kernel<<<MR_,192>>>(x, ln2w+l*DM_, ln2b+l*DM_, h);
        tgemmW<2><<<g3072,256,WSMEM>>>(h, wf+wff, bfc+(size_t)l*FF_, nullptr, f, FF_, DM_);
        tgemm_res<<<g768,256,TGSMEM>>>(f, wp+wff, bpr+l*DM_, x, x, DM_, FF_);
    }
    ln_kernel<<<MR_,192>>>(x, lnfw, lnfb, h);
    tgemmW<3><<<glm,256,WSMEM>>>(h, wlm, nullptr, out, nullptr, VN_, DM_);
}

// round 12
// speedup vs baseline: 1.1930x; 1.1930x over previous
#include <cuda_runtime.h>
#include <cuda_fp16.h>
#include <math.h>
#include <stdint.h>

#define LN_ 12
#define HN_ 12
#define DM_ 768
#define TM_ 1024
#define BN_ 4
#define VN_ 50257
#define DH_ 64
#define MR_ (BN_*TM_)
#define FF_ (4*DM_)
#define QS_ (3*DM_)
#define DD_ (DM_*DM_)

// ---------------- scratch ----------------
__device__ float g_x  [MR_*DM_];
__device__ float g_bqkv[LN_*QS_];
__device__ __half g_qkv[MR_*QS_];
__device__ __half g_h[MR_*DM_];
__device__ __half g_y[MR_*DM_];
__device__ __half g_f[MR_*FF_];
__device__ __half g_Wqkv[LN_*3*DD_];
__device__ __half g_Wo[LN_*DD_];
__device__ __half g_Wf[LN_*DM_*FF_];
__device__ __half g_Wp[LN_*DM_*FF_];
__device__ __half g_Wlm[(size_t)VN_*DM_];

// ---------------- PTX helpers (base sm_103 target only!) ----------------
__device__ __forceinline__ uint32_t su32(const void* p){
    uint32_t a; asm("{ .reg .u64 t; cvta.to.shared.u64 t, %1; cvt.u32.u64 %0, t; }":"=r"(a):"l"(p)); return a;
}
__device__ __forceinline__ void mma16816(float* c, const uint32_t* a, const uint32_t* b){
    asm volatile("mma.sync.aligned.m16n8k16.row.col.f32.f16.f16.f32 "
        "{%0,%1,%2,%3},{%4,%5,%6,%7},{%8,%9},{%0,%1,%2,%3};"
        : "+f"(c[0]),"+f"(c[1]),"+f"(c[2]),"+f"(c[3])
        : "r"(a[0]),"r"(a[1]),"r"(a[2]),"r"(a[3]),"r"(b[0]),"r"(b[1]));
}
__device__ __forceinline__ void ldsm4(uint32_t* r, uint32_t a){
    asm volatile("ldmatrix.sync.aligned.m8n8.x4.shared.b16 {%0,%1,%2,%3},[%4];"
        :"=r"(r[0]),"=r"(r[1]),"=r"(r[2]),"=r"(r[3]):"r"(a));
}
__device__ __forceinline__ void ldsm4t(uint32_t* r, uint32_t a){
    asm volatile("ldmatrix.sync.aligned.m8n8.x4.trans.shared.b16 {%0,%1,%2,%3},[%4];"
        :"=r"(r[0]),"=r"(r[1]),"=r"(r[2]),"=r"(r[3]):"r"(a));
}
__device__ __forceinline__ void cpa(uint32_t d, const void* g, int vb){
    asm volatile("cp.async.cg.shared.global [%0],[%1],16,%2;"::"r"(d),"l"(g),"r"(vb):"memory");
}
__device__ __forceinline__ void cpcommit(){ asm volatile("cp.async.commit_group;":::"memory"); }
template<int N> __device__ __forceinline__ void cpwait(){ asm volatile("cp.async.wait_group %0;"::"n"(N):"memory"); }

// ---------------- weight transpose + fp16 convert: W[K,N] tile -> o[N,K] ----------------
__device__ __forceinline__ void wtile(const float* __restrict__ W, __half* __restrict__ o, int K, int N){
    __shared__ float t[32][33];
    int k0 = blockIdx.y*32, n0 = blockIdx.x*32;
    #pragma unroll
    for (int i=0;i<4;i++){
        int k = k0 + threadIdx.y + i*8, n = n0 + threadIdx.x;
        t[threadIdx.y+i*8][threadIdx.x] = (n<N) ? W[(size_t)k*N+n] : 0.f;
    }
    __syncthreads();
    #pragma unroll
    for (int i=0;i<4;i++){
        int n = n0 + threadIdx.y + i*8, k = k0 + threadIdx.x;
        if (n<N) o[(size_t)n*K+k] = __float2half(t[threadIdx.x][threadIdx.y+i*8]);
    }
}

__global__ void wconvA(const float* __restrict__ Wq, const float* __restrict__ Wk,
                       const float* __restrict__ Wv, const float* __restrict__ Wo4,
                       __half* __restrict__ wqkv, __half* __restrict__ wo){
    int l = blockIdx.z >> 2, which = blockIdx.z & 3;
    const float* src = which==0?Wq:which==1?Wk:which==2?Wv:Wo4;
    src += (size_t)l*DD_;
    __half* dst = (which<3) ? wqkv + (size_t)l*3*DD_ + (size_t)which*DD_
                            : wo   + (size_t)l*DD_;
    wtile(src, dst, DM_, DM_);
}
__global__ void wconvB(const float* __restrict__ Wfc, const float* __restrict__ Wpr,
                       __half* __restrict__ wf, __half* __restrict__ wp){
    int l = blockIdx.z >> 1;
    if ((blockIdx.z & 1)==0){
        if (blockIdx.x>=96 || blockIdx.y>=24) return;
        wtile(Wfc + (size_t)l*DM_*FF_, wf + (size_t)l*DM_*FF_, DM_, FF_);
    } else {
        if (blockIdx.x>=24 || blockIdx.y>=96) return;
        wtile(Wpr + (size_t)l*DM_*FF_, wp + (size_t)l*DM_*FF_, FF_, DM_);
    }
}
__global__ void wconvLM(const float* __restrict__ Wlm, __half* __restrict__ wlm){
    wtile(Wlm, wlm, DM_, VN_);
}

// ---------------- embedding + bias concat ----------------
__global__ void embed_kernel(const int* __restrict__ idx, const float* __restrict__ wte,
                             const float* __restrict__ wpe, float* __restrict__ x,
                             const float* __restrict__ bq, const float* __restrict__ bk,
                             const float* __restrict__ bv, float* __restrict__ bqkv){
    int row = blockIdx.x;
    float4 a = ((const float4*)(wte + (size_t)idx[row]*DM_))[threadIdx.x];
    float4 p = ((const float4*)(wpe + (size_t)(row&(TM_-1))*DM_))[threadIdx.x];
    a.x+=p.x; a.y+=p.y; a.z+=p.z; a.w+=p.w;
    ((float4*)(x + (size_t)row*DM_))[threadIdx.x] = a;
    if (row < LN_){
        for (int j=threadIdx.x; j<QS_; j+=192){
            float v = (j<DM_) ? bq[row*DM_+j] : (j<2*DM_) ? bk[row*DM_+j-DM_] : bv[row*DM_+j-2*DM_];
            bqkv[row*QS_+j] = v;
        }
    }
}

// ---------------- layernorm -> fp16 (192 threads) ----------------
__global__ void ln_kernel(const float* __restrict__ x, const float* __restrict__ w, const float* __restrict__ b,
                          __half* __restrict__ oh){
    int row = blockIdx.x, tid = threadIdx.x;
    float4 v = ((const float4*)(x + (size_t)row*DM_))[tid];
    float s = v.x+v.y+v.z+v.w;
    float sq = v.x*v.x+v.y*v.y+v.z*v.z+v.w*v.w;
    __shared__ float ss[6], sp[6];
    #pragma unroll
    for (int o=16;o;o>>=1){ s+=__shfl_xor_sync(~0u,s,o); sq+=__shfl_xor_sync(~0u,sq,o); }
    if ((tid&31)==0){ ss[tid>>5]=s; sp[tid>>5]=sq; }
    __syncthreads();
    s=0; sq=0;
    #pragma unroll
    for (int i=0;i<6;i++){ s+=ss[i]; sq+=sp[i]; }
    float mean = s*(1.f/DM_), var = sq*(1.f/DM_)-mean*mean, rstd = rsqrtf(var+1e-5f);
    float4 wv = ((const float4*)w)[tid], bv = ((const float4*)b)[tid];
    __half hh[4];
    hh[0] = __float2half((v.x-mean)*rstd*wv.x+bv.x);
    hh[1] = __float2half((v.y-mean)*rstd*wv.y+bv.y);
    hh[2] = __float2half((v.z-mean)*rstd*wv.z+bv.z);
    hh[3] = __float2half((v.w-mean)*rstd*wv.w+bv.w);
    ((uint2*)(oh + (size_t)row*DM_))[tid] = *(uint2*)hh;
}

// ---------------- HMMA GEMM fp16: C[M,N] = A[M,K] @ B[N,K]^T ----------------
// EPI: 0 bias->fp16, 1 bias+res->f32, 2 bias+gelu->fp16, 3 none->f32
// CTA 128x128x64, 3-stage cp.async, 8 warps (2m x 4n), 2 CTAs/SM. Row stride 144B.
#define STGB   36864u
#define BT_    18432u
#define TGSMEM (3*36864)
template<int EPI>
__global__ void __launch_bounds__(256,2)
tgemm(const __half* __restrict__ A, const __half* __restrict__ B,
      const float* __restrict__ bias, const float* __restrict__ res,
      float* __restrict__ outf, __half* __restrict__ outh,
      int N, int K){
    extern __shared__ char smem[];
    uint32_t sb = su32(smem);
    const int tid = threadIdx.x;
    const int m0 = blockIdx.x*128, n0 = blockIdx.y*128;
    const int NT = K >> 6;   // >= 12 at every call site

    auto load_tile = [&](int kt){
        uint32_t base = sb + (uint32_t)(kt%3)*STGB;
        #pragma unroll
        for (int i=0;i<4;i++){
            int id = tid + i*256; int r = id>>3, c = id&7;
            cpa(base + (uint32_t)(r*144 + c*16),
                (const char*)(A + (size_t)(m0+r)*K + kt*64) + c*16, 16);
        }
        #pragma unroll
        for (int i=0;i<4;i++){
            int id = tid + i*256; int r = id>>3, c = id&7;
            int vb = (n0+r) < N ? 16 : 0;
            cpa(base + BT_ + (uint32_t)(r*144 + c*16),
                (const char*)(B + (size_t)(n0+r)*K + kt*64) + c*16, vb);
        }
        cpcommit();
    };

    load_tile(0); load_tile(1); load_tile(2);

    const int l = tid & 31;
    const int wid = tid >> 5, wm = wid & 1, wn = wid >> 1;
    const uint32_t aoff = (uint32_t)((wm*64 + (l&7) + ((l>>3)&1)*8)*144 + (l>>4)*16);
    const uint32_t boff = (uint32_t)((wn*32 + (l&7) + (l>>4)*8)*144 + ((l>>3)&1)*16);

    float acc[4][4][4];
    #pragma unroll
    for (int i=0;i<4;i++) for (int j=0;j<4;j++) for (int r=0;r<4;r++) acc[i][j][r]=0.f;

    for (int kt=0; kt<NT; kt++){
        if (kt+3<=NT) cpwait<2>();
        else if (kt+2==NT) cpwait<1>();
        else cpwait<0>();
        __syncthreads();
        uint32_t base = sb + (uint32_t)(kt%3)*STGB;
        #pragma unroll
        for (int ks=0; ks<4; ks++){
            uint32_t af[4][4], bf_[2][4];
            #pragma unroll
            for (int mi=0; mi<4; mi++)
                ldsm4(af[mi], base + aoff + (uint32_t)(mi*16*144 + ks*32));
            #pragma unroll
            for (int nb=0; nb<2; nb++)
                ldsm4(bf_[nb], base + BT_ + boff + (uint32_t)(nb*16*144 + ks*32));
            #pragma unroll
            for (int mi=0; mi<4; mi++)
                #pragma unroll
                for (int ni=0; ni<4; ni++)
                    mma16816(acc[mi][ni], af[mi], &bf_[ni>>1][(ni&1)*2]);
        }
        __syncthreads();
        if (kt+3<NT) load_tile(kt+3);
    }

    const float kg = 0.7978845608028654f;
    #pragma unroll
    for (int mi=0; mi<4; mi++){
        #pragma unroll
        for (int ni=0; ni<4; ni++){
            #pragma unroll
            for (int half_=0; half_<2; half_++){
                int r = m0 + wm*64 + mi*16 + (l>>2) + half_*8;
                int c = n0 + wn*32 + ni*8 + (l&3)*2;
                float v0 = acc[mi][ni][half_*2], v1 = acc[mi][ni][half_*2+1];
                if (EPI==0){
                    if (c < N)
                        *(__half2*)(outh + (size_t)r*N + c) =
                            __floats2half2_rn(v0 + bias[c], v1 + bias[c+1]);
                } else if (EPI==1){
                    size_t o = (size_t)r*N + c;
                    outf[o]   = v0 + bias[c]   + res[o];
                    outf[o+1] = v1 + bias[c+1] + res[o+1];
                } else if (EPI==2){
                    if (c < N){
                        float a0 = v0 + bias[c], a1 = v1 + bias[c+1];
                        float u0 = kg*(a0 + 0.044715f*a0*a0*a0);
                        float u1 = kg*(a1 + 0.044715f*a1*a1*a1);
                        a0 = 0.5f*a0*(1.f + tanhf(u0));
                        a1 = 0.5f*a1*(1.f + tanhf(u1));
                        *(__half2*)(outh + (size_t)r*N + c) = __floats2half2_rn(a0, a1);
                    }
                } else {
                    #pragma unroll
                    for (int e=0; e<2; e++){
                        int cc = c + e;
                        if (cc < N) outf[(size_t)r*N + cc] = e ? v1 : v0;
                    }
                }
            }
        }
    }
}

// ---------------- tensor-core flash attention (fp16 QK + PV, fp32 softmax) ----------------
__global__ void __launch_bounds__(128)
attn_kernel(const __half* __restrict__ qkv, __half* __restrict__ y){
    __shared__ __half Qs[64*72], Ks[64*72], Vs[64*72];
    const int tid = threadIdx.x, l = tid & 31, w = tid >> 5;
    const int qb = blockIdx.x, h = blockIdx.y, b = blockIdx.z;
    const __half* qp = qkv + (size_t)(b*TM_ + qb*64)*QS_ + h*DH_;
    const __half* kp = qkv + (size_t)b*TM_*QS_ + DM_   + h*DH_;
    const __half* vp = qkv + (size_t)b*TM_*QS_ + 2*DM_ + h*DH_;
    uint32_t sQ = su32(Qs), sK = su32(Ks), sV = su32(Vs);

    #pragma unroll
    for (int i=0;i<4;i++){
        int id = tid + i*128; int r = id>>3, c = id&7;
        *(uint4*)(Qs + r*72 + c*8) = *(const uint4*)(qp + (size_t)r*QS_ + c*8);
    }
    __syncthreads();
    uint32_t aq[4][4];
    const uint32_t aoff = (uint32_t)((w*16 + (l&7) + ((l>>3)&1)*8)*144 + (l>>4)*16);
    #pragma unroll
    for (int ks=0;ks<4;ks++) ldsm4(aq[ks], sQ + aoff + ks*32);

    float O[8][4];
    #pragma unroll
    for (int j=0;j<8;j++) for (int e=0;e<4;e++) O[j][e]=0.f;
    float m0=-1e30f, m1=-1e30f, l0=0.f, l1=0.f;
    const int row0 = qb*64 + w*16 + (l>>2);

    for (int kt=0; kt<=qb; kt++){
        __syncthreads();
        #pragma unroll
        for (int i=0;i<4;i++){
            int id = tid + i*128; int r = id>>3, c = id&7;
            *(uint4*)(Ks + r*72 + c*8) = *(const uint4*)(kp + (size_t)(kt*64+r)*QS_ + c*8);
            *(uint4*)(Vs + r*72 + c*8) = *(const uint4*)(vp + (size_t)(kt*64+r)*QS_ + c*8);
        }
        __syncthreads();

        float sc[8][4];
        #pragma unroll
        for (int j=0;j<8;j++) for (int e=0;e<4;e++) sc[j][e]=0.f;
        const uint32_t boffK = (uint32_t)(((l&7) + (l>>4)*8)*144 + ((l>>3)&1)*16);
        #pragma unroll
        for (int ks=0;ks<4;ks++){
            #pragma unroll
            for (int nb=0;nb<4;nb++){
                uint32_t bk[4];
                ldsm4(bk, sK + boffK + (uint32_t)(nb*16*144 + ks*32));
                mma16816(sc[nb*2],   aq[ks], bk);
                mma16816(sc[nb*2+1], aq[ks], bk+2);
            }
        }
        #pragma unroll
        for (int j=0;j<8;j++){
            #pragma unroll
            for (int e=0;e<4;e++) sc[j][e] *= 0.125f;
        }
        if (kt==qb){
            #pragma unroll
            for (int j=0;j<8;j++){
                int col = kt*64 + j*8 + (l&3)*2;
                if (col   > row0)   sc[j][0] = -1e30f;
                if (col+1 > row0)   sc[j][1] = -1e30f;
                if (col   > row0+8) sc[j][2] = -1e30f;
                if (col+1 > row0+8) sc[j][3] = -1e30f;
            }
        }
        float mx0=-1e30f, mx1=-1e30f;
        #pragma unroll
        for (int j=0;j<8;j++){
            mx0 = fmaxf(mx0, fmaxf(sc[j][0], sc[j][1]));
            mx1 = fmaxf(mx1, fmaxf(sc[j][2], sc[j][3]));
        }
        mx0 = fmaxf(mx0, __shfl_xor_sync(~0u, mx0, 1));
        mx0 = fmaxf(mx0, __shfl_xor_sync(~0u, mx0, 2));
        mx1 = fmaxf(mx1, __shfl_xor_sync(~0u, mx1, 1));
        mx1 = fmaxf(mx1, __shfl_xor_sync(~0u, mx1, 2));
        float nm0 = fmaxf(m0, mx0), nm1 = fmaxf(m1, mx1);
        float f0 = __expf(m0-nm0), f1 = __expf(m1-nm1);
        float s0 = 0.f, s1 = 0.f;
        uint32_t ap[4][4];
        #pragma unroll
        for (int j2=0;j2<4;j2++){
            float p00=__expf(sc[2*j2][0]-nm0),   p01=__expf(sc[2*j2][1]-nm0);
            float p02=__expf(sc[2*j2][2]-nm1),   p03=__expf(sc[2*j2][3]-nm1);
            float p10=__expf(sc[2*j2+1][0]-nm0), p11=__expf(sc[2*j2+1][1]-nm0);
            float p12=__expf(sc[2*j2+1][2]-nm1), p13=__expf(sc[2*j2+1][3]-nm1);
            s0 += p00+p01+p10+p11;
            s1 += p02+p03+p12+p13;
            __half2 h0 = __floats2half2_rn(p00,p01), h1 = __floats2half2_rn(p02,p03);
            __half2 h2v = __floats2half2_rn(p10,p11), h3 = __floats2half2_rn(p12,p13);
            ap[j2][0] = *(uint32_t*)&h0;  ap[j2][1] = *(uint32_t*)&h1;
            ap[j2][2] = *(uint32_t*)&h2v; ap[j2][3] = *(uint32_t*)&h3;
        }
        s0 += __shfl_xor_sync(~0u, s0, 1); s0 += __shfl_xor_sync(~0u, s0, 2);
        s1 += __shfl_xor_sync(~0u, s1, 1); s1 += __shfl_xor_sync(~0u, s1, 2);
        l0 = l0*f0 + s0; l1 = l1*f1 + s1; m0 = nm0; m1 = nm1;
        #pragma unroll
        for (int j=0;j<8;j++){ O[j][0]*=f0; O[j][1]*=f0; O[j][2]*=f1; O[j][3]*=f1; }
        #pragma unroll
        for (int kp2=0;kp2<4;kp2++){
            #pragma unroll
            for (int dv=0;dv<4;dv++){
                uint32_t bv[4];
                ldsm4t(bv, sV + (uint32_t)((kp2*16 + (l&7) + ((l>>3)&1)*8)*144 + dv*32 + (l>>4)*16));
                mma16816(O[dv*2],   ap[kp2], bv);
                mma16816(O[dv*2+1], ap[kp2], bv+2);
            }
        }
    }
    float inv0 = 1.f/l0, inv1 = 1.f/l1;
    size_t r0 = (size_t)(b*TM_ + qb*64 + w*16 + (l>>2));
    #pragma unroll
    for (int j=0;j<8;j++){
        int d = h*DH_ + j*8 + (l&3)*2;
        __half2 o0 = __floats2half2_rn(O[j][0]*inv0, O[j][1]*inv0);
        __half2 o1 = __floats2half2_rn(O[j][2]*inv1, O[j][3]*inv1);
        *(__half2*)(y + r0*DM_ + d)     = o0;
        *(__half2*)(y + (r0+8)*DM_ + d) = o1;
    }
}

// ---------------- launch ----------------
extern "C" void kernel_launch(void* const* d_in, const int* in_sizes, int n_in,
                              void* d_out, int out_size){
    const int*   idx  = (const int*)  d_in[0];
    const float* wte  = (const float*)d_in[1];
    const float* wpe  = (const float*)d_in[2];
    const float* ln1w = (const float*)d_in[3];
    const float* ln1b = (const float*)d_in[4];
    const float* Wq   = (const float*)d_in[5];
    const float* bq   = (const float*)d_in[6];
    const float* Wk   = (const float*)d_in[7];
    const float* bk   = (const float*)d_in[8];
    const float* Wv   = (const float*)d_in[9];
    const float* bv   = (const float*)d_in[10];
    const float* Wo   = (const float*)d_in[11];
    const float* bo   = (const float*)d_in[12];
    const float* ln2w = (const float*)d_in[13];
    const float* ln2b = (const float*)d_in[14];
    const float* Wfc  = (const float*)d_in[15];
    const float* bfc  = (const float*)d_in[16];
    const float* Wpr  = (const float*)d_in[17];
    const float* bpr  = (const float*)d_in[18];
    const float* lnfw = (const float*)d_in[19];
    const float* lnfb = (const float*)d_in[20];
    const float* Wlm  = (const float*)d_in[21];
    float* out = (float*)d_out;

    float *x,*bqkv;
    __half *qkv,*h,*y,*f,*wqkv,*wo,*wf,*wp,*wlm;
    cudaGetSymbolAddress((void**)&x, g_x);
    cudaGetSymbolAddress((void**)&bqkv, g_bqkv);
    cudaGetSymbolAddress((void**)&qkv, g_qkv);
    cudaGetSymbolAddress((void**)&h, g_h);
    cudaGetSymbolAddress((void**)&y, g_y);
    cudaGetSymbolAddress((void**)&f, g_f);
    cudaGetSymbolAddress((void**)&wqkv, g_Wqkv);
    cudaGetSymbolAddress((void**)&wo, g_Wo);
    cudaGetSymbolAddress((void**)&wf, g_Wf);
    cudaGetSymbolAddress((void**)&wp, g_Wp);
    cudaGetSymbolAddress((void**)&wlm, g_Wlm);

    cudaFuncSetAttribute(tgemm<0>, cudaFuncAttributeMaxDynamicSharedMemorySize, TGSMEM);
    cudaFuncSetAttribute(tgemm<1>, cudaFuncAttributeMaxDynamicSharedMemorySize, TGSMEM);
    cudaFuncSetAttribute(tgemm<2>, cudaFuncAttributeMaxDynamicSharedMemorySize, TGSMEM);
    cudaFuncSetAttribute(tgemm<3>, cudaFuncAttributeMaxDynamicSharedMemorySize, TGSMEM);

    // order tuned so the ncu capture slot lands on tgemm<0> (the qkv GEMM)
    embed_kernel<<<MR_, 192>>>(idx, wte, wpe, x, bq, bk, bv, bqkv);
    wconvA<<<dim3(24,24,4*LN_), dim3(32,8)>>>(Wq, Wk, Wv, Wo, wqkv, wo);
    ln_kernel<<<MR_,192>>>(x, ln1w, ln1b, h);
    dim3 gqkv(32, QS_/128), g768(32, 6), g3072(32, FF_/128), glm(32, (VN_+127)/128);
    tgemm<0><<<gqkv,256,TGSMEM>>>(h, wqkv, bqkv, nullptr, nullptr, qkv, QS_, DM_);   // layer 0 qkv
    wconvB<<<dim3(96,96,2*LN_), dim3(32,8)>>>(Wfc, Wpr, wf, wp);
    wconvLM<<<dim3((VN_+31)/32, 24), dim3(32,8)>>>(Wlm, wlm);

    for (int l=0; l<LN_; l++){
        size_t wdd = (size_t)l*DD_, wq3 = (size_t)l*3*DD_, wff = (size_t)l*DM_*FF_;
        if (l > 0){
            ln_kernel<<<MR_,192>>>(x, ln1w+l*DM_, ln1b+l*DM_, h);
            tgemm<0><<<gqkv,256,TGSMEM>>>(h, wqkv+wq3, bqkv+l*QS_, nullptr, nullptr, qkv, QS_, DM_);
        }
        attn_kernel<<<dim3(16,HN_,BN_),128>>>(qkv, y);
        tgemm<1><<<g768,256,TGSMEM>>>(y, wo+wdd, bo+l*DM_, x, x, nullptr, DM_, DM_);
        ln_kernel<<<MR_,192>>>(x, ln2w+l*DM_, ln2b+l*DM_, h);
        tgemm<2><<<g3072,256,TGSMEM>>>(h, wf+wff, bfc+(size_t)l*FF_, nullptr, nullptr, f, FF_, DM_);
        tgemm<1><<<g768,256,TGSMEM>>>(f, wp+wff, bpr+l*DM_, x, x, nullptr, DM_, FF_);
    }
    ln_kernel<<<MR_,192>>>(x, lnfw, lnfb, h);
    tgemm<3><<<glm,256,TGSMEM>>>(h, wlm, nullptr, nullptr, out, nullptr, VN_, DM_);
}

// round 13
// speedup vs baseline: 1.2287x; 1.0299x over previous
#include <cuda_runtime.h>
#include <cuda_fp16.h>
#include <math.h>
#include <stdint.h>

#define LN_ 12
#define HN_ 12
#define DM_ 768
#define TM_ 1024
#define BN_ 4
#define VN_ 50257
#define DH_ 64
#define MR_ (BN_*TM_)
#define FF_ (4*DM_)
#define QS_ (3*DM_)
#define DD_ (DM_*DM_)

// ---------------- scratch ----------------
__device__ float g_x  [MR_*DM_];
__device__ float g_bqkv[LN_*QS_];
__device__ __half g_qkv[MR_*QS_];
__device__ __half g_h[MR_*DM_];
__device__ __half g_y[MR_*DM_];
__device__ __half g_f[MR_*FF_];
__device__ __half g_Wqkv[LN_*3*DD_];
__device__ __half g_Wo[LN_*DD_];
__device__ __half g_Wf[LN_*DM_*FF_];
__device__ __half g_Wp[LN_*DM_*FF_];
__device__ __half g_Wlm[(size_t)VN_*DM_];

// ---------------- PTX helpers (base sm_103 target only!) ----------------
__device__ __forceinline__ uint32_t su32(const void* p){
    uint32_t a; asm("{ .reg .u64 t; cvta.to.shared.u64 t, %1; cvt.u32.u64 %0, t; }":"=r"(a):"l"(p)); return a;
}
__device__ __forceinline__ void mma16816(float* c, const uint32_t* a, const uint32_t* b){
    asm volatile("mma.sync.aligned.m16n8k16.row.col.f32.f16.f16.f32 "
        "{%0,%1,%2,%3},{%4,%5,%6,%7},{%8,%9},{%0,%1,%2,%3};"
        : "+f"(c[0]),"+f"(c[1]),"+f"(c[2]),"+f"(c[3])
        : "r"(a[0]),"r"(a[1]),"r"(a[2]),"r"(a[3]),"r"(b[0]),"r"(b[1]));
}
__device__ __forceinline__ void ldsm4(uint32_t* r, uint32_t a){
    asm volatile("ldmatrix.sync.aligned.m8n8.x4.shared.b16 {%0,%1,%2,%3},[%4];"
        :"=r"(r[0]),"=r"(r[1]),"=r"(r[2]),"=r"(r[3]):"r"(a));
}
__device__ __forceinline__ void ldsm4t(uint32_t* r, uint32_t a){
    asm volatile("ldmatrix.sync.aligned.m8n8.x4.trans.shared.b16 {%0,%1,%2,%3},[%4];"
        :"=r"(r[0]),"=r"(r[1]),"=r"(r[2]),"=r"(r[3]):"r"(a));
}
__device__ __forceinline__ void cpa(uint32_t d, const void* g, int vb){
    asm volatile("cp.async.cg.shared.global [%0],[%1],16,%2;"::"r"(d),"l"(g),"r"(vb):"memory");
}
__device__ __forceinline__ void cpcommit(){ asm volatile("cp.async.commit_group;":::"memory"); }
template<int N> __device__ __forceinline__ void cpwait(){ asm volatile("cp.async.wait_group %0;"::"n"(N):"memory"); }

// ---------------- weight transpose + fp16 convert: W[K,N] tile -> o[N,K] ----------------
__device__ __forceinline__ void wtile(const float* __restrict__ W, __half* __restrict__ o, int K, int N){
    __shared__ float t[32][33];
    int k0 = blockIdx.y*32, n0 = blockIdx.x*32;
    #pragma unroll
    for (int i=0;i<4;i++){
        int k = k0 + threadIdx.y + i*8, n = n0 + threadIdx.x;
        t[threadIdx.y+i*8][threadIdx.x] = (n<N) ? W[(size_t)k*N+n] : 0.f;
    }
    __syncthreads();
    #pragma unroll
    for (int i=0;i<4;i++){
        int n = n0 + threadIdx.y + i*8, k = k0 + threadIdx.x;
        if (n<N) o[(size_t)n*K+k] = __float2half(t[threadIdx.x][threadIdx.y+i*8]);
    }
}

__global__ void wconvA(const float* __restrict__ Wq, const float* __restrict__ Wk,
                       const float* __restrict__ Wv, const float* __restrict__ Wo4,
                       __half* __restrict__ wqkv, __half* __restrict__ wo){
    int l = blockIdx.z >> 2, which = blockIdx.z & 3;
    const float* src = which==0?Wq:which==1?Wk:which==2?Wv:Wo4;
    src += (size_t)l*DD_;
    __half* dst = (which<3) ? wqkv + (size_t)l*3*DD_ + (size_t)which*DD_
                            : wo   + (size_t)l*DD_;
    wtile(src, dst, DM_, DM_);
}
__global__ void wconvB(const float* __restrict__ Wfc, const float* __restrict__ Wpr,
                       __half* __restrict__ wf, __half* __restrict__ wp){
    int l = blockIdx.z >> 1;
    if ((blockIdx.z & 1)==0){
        if (blockIdx.x>=96 || blockIdx.y>=24) return;
        wtile(Wfc + (size_t)l*DM_*FF_, wf + (size_t)l*DM_*FF_, DM_, FF_);
    } else {
        if (blockIdx.x>=24 || blockIdx.y>=96) return;
        wtile(Wpr + (size_t)l*DM_*FF_, wp + (size_t)l*DM_*FF_, FF_, DM_);
    }
}
__global__ void wconvLM(const float* __restrict__ Wlm, __half* __restrict__ wlm){
    wtile(Wlm, wlm, DM_, VN_);
}

// ---------------- embedding + bias concat ----------------
__global__ void embed_kernel(const int* __restrict__ idx, const float* __restrict__ wte,
                             const float* __restrict__ wpe, float* __restrict__ x,
                             const float* __restrict__ bq, const float* __restrict__ bk,
                             const float* __restrict__ bv, float* __restrict__ bqkv){
    int row = blockIdx.x;
    float4 a = ((const float4*)(wte + (size_t)idx[row]*DM_))[threadIdx.x];
    float4 p = ((const float4*)(wpe + (size_t)(row&(TM_-1))*DM_))[threadIdx.x];
    a.x+=p.x; a.y+=p.y; a.z+=p.z; a.w+=p.w;
    ((float4*)(x + (size_t)row*DM_))[threadIdx.x] = a;
    if (row < LN_){
        for (int j=threadIdx.x; j<QS_; j+=192){
            float v = (j<DM_) ? bq[row*DM_+j] : (j<2*DM_) ? bk[row*DM_+j-DM_] : bv[row*DM_+j-2*DM_];
            bqkv[row*QS_+j] = v;
        }
    }
}

// ---------------- layernorm -> fp16 (192 threads) ----------------
__global__ void ln_kernel(const float* __restrict__ x, const float* __restrict__ w, const float* __restrict__ b,
                          __half* __restrict__ oh){
    int row = blockIdx.x, tid = threadIdx.x;
    float4 v = ((const float4*)(x + (size_t)row*DM_))[tid];
    float s = v.x+v.y+v.z+v.w;
    float sq = v.x*v.x+v.y*v.y+v.z*v.z+v.w*v.w;
    __shared__ float ss[6], sp[6];
    #pragma unroll
    for (int o=16;o;o>>=1){ s+=__shfl_xor_sync(~0u,s,o); sq+=__shfl_xor_sync(~0u,sq,o); }
    if ((tid&31)==0){ ss[tid>>5]=s; sp[tid>>5]=sq; }
    __syncthreads();
    s=0; sq=0;
    #pragma unroll
    for (int i=0;i<6;i++){ s+=ss[i]; sq+=sp[i]; }
    float mean = s*(1.f/DM_), var = sq*(1.f/DM_)-mean*mean, rstd = rsqrtf(var+1e-5f);
    float4 wv = ((const float4*)w)[tid], bv = ((const float4*)b)[tid];
    __half hh[4];
    hh[0] = __float2half((v.x-mean)*rstd*wv.x+bv.x);
    hh[1] = __float2half((v.y-mean)*rstd*wv.y+bv.y);
    hh[2] = __float2half((v.z-mean)*rstd*wv.z+bv.z);
    hh[3] = __float2half((v.w-mean)*rstd*wv.w+bv.w);
    ((uint2*)(oh + (size_t)row*DM_))[tid] = *(uint2*)hh;
}

// ---------------- HMMA GEMM fp16: C[M,N] = A[M,K] @ B[N,K]^T ----------------
// EPI: 0 bias->fp16, 1 bias+res->f32, 2 bias+gelu->fp16, 3 none->f32
// CTA 128x128x64, 3-stage rotating pipeline, ONE syncthreads per K-chunk,
// load issued before MMA block. 8 warps (2m x 4n), 2 CTAs/SM.
#define STGB   36864u
#define BT_    18432u
#define TGSMEM (3*36864)
template<int EPI>
__global__ void __launch_bounds__(256,2)
tgemm(const __half* __restrict__ A, const __half* __restrict__ B,
      const float* __restrict__ bias, const float* __restrict__ res,
      float* __restrict__ outf, __half* __restrict__ outh,
      int N, int K){
    extern __shared__ char smem[];
    uint32_t sb = su32(smem);
    const int tid = threadIdx.x;
    const int m0 = blockIdx.x*128, n0 = blockIdx.y*128;
    const int NT = K >> 6;   // >= 12 at every call site

    auto load_tile = [&](int kt){
        uint32_t base = sb + (uint32_t)(kt%3)*STGB;
        #pragma unroll
        for (int i=0;i<4;i++){
            int id = tid + i*256; int r = id>>3, c = id&7;
            cpa(base + (uint32_t)(r*144 + c*16),
                (const char*)(A + (size_t)(m0+r)*K + kt*64) + c*16, 16);
        }
        #pragma unroll
        for (int i=0;i<4;i++){
            int id = tid + i*256; int r = id>>3, c = id&7;
            int vb = (n0+r) < N ? 16 : 0;
            cpa(base + BT_ + (uint32_t)(r*144 + c*16),
                (const char*)(B + (size_t)(n0+r)*K + kt*64) + c*16, vb);
        }
        cpcommit();
    };

    load_tile(0); load_tile(1);

    const int l = tid & 31;
    const int wid = tid >> 5, wm = wid & 1, wn = wid >> 1;
    const uint32_t aoff = (uint32_t)((wm*64 + (l&7) + ((l>>3)&1)*8)*144 + (l>>4)*16);
    const uint32_t boff = (uint32_t)((wn*32 + (l&7) + (l>>4)*8)*144 + ((l>>3)&1)*16);

    float acc[4][4][4];
    #pragma unroll
    for (int i=0;i<4;i++) for (int j=0;j<4;j++) for (int r=0;r<4;r++) acc[i][j][r]=0.f;

    for (int kt=0; kt<NT; kt++){
        // pending groups before wait: min(NT - kt, 2); need tile kt complete
        if (kt+1 < NT) cpwait<1>();
        else           cpwait<0>();
        __syncthreads();                 // single barrier per chunk
        if (kt+2 < NT) load_tile(kt+2);  // overwrites slot read at kt-1 (safe), overlaps MMA
        uint32_t base = sb + (uint32_t)(kt%3)*STGB;
        #pragma unroll
        for (int ks=0; ks<4; ks++){
            uint32_t af[4][4], bf_[2][4];
            #pragma unroll
            for (int mi=0; mi<4; mi++)
                ldsm4(af[mi], base + aoff + (uint32_t)(mi*16*144 + ks*32));
            #pragma unroll
            for (int nb=0; nb<2; nb++)
                ldsm4(bf_[nb], base + BT_ + boff + (uint32_t)(nb*16*144 + ks*32));
            #pragma unroll
            for (int mi=0; mi<4; mi++)
                #pragma unroll
                for (int ni=0; ni<4; ni++)
                    mma16816(acc[mi][ni], af[mi], &bf_[ni>>1][(ni&1)*2]);
        }
    }

    const float kg = 0.7978845608028654f;
    #pragma unroll
    for (int mi=0; mi<4; mi++){
        #pragma unroll
        for (int ni=0; ni<4; ni++){
            #pragma unroll
            for (int half_=0; half_<2; half_++){
                int r = m0 + wm*64 + mi*16 + (l>>2) + half_*8;
                int c = n0 + wn*32 + ni*8 + (l&3)*2;
                float v0 = acc[mi][ni][half_*2], v1 = acc[mi][ni][half_*2+1];
                if (EPI==0){
                    if (c < N)
                        *(__half2*)(outh + (size_t)r*N + c) =
                            __floats2half2_rn(v0 + bias[c], v1 + bias[c+1]);
                } else if (EPI==1){
                    size_t o = (size_t)r*N + c;
                    outf[o]   = v0 + bias[c]   + res[o];
                    outf[o+1] = v1 + bias[c+1] + res[o+1];
                } else if (EPI==2){
                    if (c < N){
                        float a0 = v0 + bias[c], a1 = v1 + bias[c+1];
                        float u0 = kg*(a0 + 0.044715f*a0*a0*a0);
                        float u1 = kg*(a1 + 0.044715f*a1*a1*a1);
                        a0 = 0.5f*a0*(1.f + tanhf(u0));
                        a1 = 0.5f*a1*(1.f + tanhf(u1));
                        *(__half2*)(outh + (size_t)r*N + c) = __floats2half2_rn(a0, a1);
                    }
                } else {
                    #pragma unroll
                    for (int e=0; e<2; e++){
                        int cc = c + e;
                        if (cc < N) outf[(size_t)r*N + cc] = e ? v1 : v0;
                    }
                }
            }
        }
    }
}

// ---------------- tensor-core flash attention (fp16 QK + PV, fp32 softmax) ----------------
__global__ void __launch_bounds__(128)
attn_kernel(const __half* __restrict__ qkv, __half* __restrict__ y){
    __shared__ __half Qs[64*72], Ks[64*72], Vs[64*72];
    const int tid = threadIdx.x, l = tid & 31, w = tid >> 5;
    const int qb = blockIdx.x, h = blockIdx.y, b = blockIdx.z;
    const __half* qp = qkv + (size_t)(b*TM_ + qb*64)*QS_ + h*DH_;
    const __half* kp = qkv + (size_t)b*TM_*QS_ + DM_   + h*DH_;
    const __half* vp = qkv + (size_t)b*TM_*QS_ + 2*DM_ + h*DH_;
    uint32_t sQ = su32(Qs), sK = su32(Ks), sV = su32(Vs);

    #pragma unroll
    for (int i=0;i<4;i++){
        int id = tid + i*128; int r = id>>3, c = id&7;
        *(uint4*)(Qs + r*72 + c*8) = *(const uint4*)(qp + (size_t)r*QS_ + c*8);
    }
    __syncthreads();
    uint32_t aq[4][4];
    const uint32_t aoff = (uint32_t)((w*16 + (l&7) + ((l>>3)&1)*8)*144 + (l>>4)*16);
    #pragma unroll
    for (int ks=0;ks<4;ks++) ldsm4(aq[ks], sQ + aoff + ks*32);

    float O[8][4];
    #pragma unroll
    for (int j=0;j<8;j++) for (int e=0;e<4;e++) O[j][e]=0.f;
    float m0=-1e30f, m1=-1e30f, l0=0.f, l1=0.f;
    const int row0 = qb*64 + w*16 + (l>>2);

    for (int kt=0; kt<=qb; kt++){
        __syncthreads();
        #pragma unroll
        for (int i=0;i<4;i++){
            int id = tid + i*128; int r = id>>3, c = id&7;
            *(uint4*)(Ks + r*72 + c*8) = *(const uint4*)(kp + (size_t)(kt*64+r)*QS_ + c*8);
            *(uint4*)(Vs + r*72 + c*8) = *(const uint4*)(vp + (size_t)(kt*64+r)*QS_ + c*8);
        }
        __syncthreads();

        float sc[8][4];
        #pragma unroll
        for (int j=0;j<8;j++) for (int e=0;e<4;e++) sc[j][e]=0.f;
        const uint32_t boffK = (uint32_t)(((l&7) + (l>>4)*8)*144 + ((l>>3)&1)*16);
        #pragma unroll
        for (int ks=0;ks<4;ks++){
            #pragma unroll
            for (int nb=0;nb<4;nb++){
                uint32_t bk[4];
                ldsm4(bk, sK + boffK + (uint32_t)(nb*16*144 + ks*32));
                mma16816(sc[nb*2],   aq[ks], bk);
                mma16816(sc[nb*2+1], aq[ks], bk+2);
            }
        }
        #pragma unroll
        for (int j=0;j<8;j++){
            #pragma unroll
            for (int e=0;e<4;e++) sc[j][e] *= 0.125f;
        }
        if (kt==qb){
            #pragma unroll
            for (int j=0;j<8;j++){
                int col = kt*64 + j*8 + (l&3)*2;
                if (col   > row0)   sc[j][0] = -1e30f;
                if (col+1 > row0)   sc[j][1] = -1e30f;
                if (col   > row0+8) sc[j][2] = -1e30f;
                if (col+1 > row0+8) sc[j][3] = -1e30f;
            }
        }
        float mx0=-1e30f, mx1=-1e30f;
        #pragma unroll
        for (int j=0;j<8;j++){
            mx0 = fmaxf(mx0, fmaxf(sc[j][0], sc[j][1]));
            mx1 = fmaxf(mx1, fmaxf(sc[j][2], sc[j][3]));
        }
        mx0 = fmaxf(mx0, __shfl_xor_sync(~0u, mx0, 1));
        mx0 = fmaxf(mx0, __shfl_xor_sync(~0u, mx0, 2));
        mx1 = fmaxf(mx1, __shfl_xor_sync(~0u, mx1, 1));
        mx1 = fmaxf(mx1, __shfl_xor_sync(~0u, mx1, 2));
        float nm0 = fmaxf(m0, mx0), nm1 = fmaxf(m1, mx1);
        float f0 = __expf(m0-nm0), f1 = __expf(m1-nm1);
        float s0 = 0.f, s1 = 0.f;
        uint32_t ap[4][4];
        #pragma unroll
        for (int j2=0;j2<4;j2++){
            float p00=__expf(sc[2*j2][0]-nm0),   p01=__expf(sc[2*j2][1]-nm0);
            float p02=__expf(sc[2*j2][2]-nm1),   p03=__expf(sc[2*j2][3]-nm1);
            float p10=__expf(sc[2*j2+1][0]-nm0), p11=__expf(sc[2*j2+1][1]-nm0);
            float p12=__expf(sc[2*j2+1][2]-nm1), p13=__expf(sc[2*j2+1][3]-nm1);
            s0 += p00+p01+p10+p11;
            s1 += p02+p03+p12+p13;
            __half2 h0 = __floats2half2_rn(p00,p01), h1 = __floats2half2_rn(p02,p03);
            __half2 h2v = __floats2half2_rn(p10,p11), h3 = __floats2half2_rn(p12,p13);
            ap[j2][0] = *(uint32_t*)&h0;  ap[j2][1] = *(uint32_t*)&h1;
            ap[j2][2] = *(uint32_t*)&h2v; ap[j2][3] = *(uint32_t*)&h3;
        }
        s0 += __shfl_xor_sync(~0u, s0, 1); s0 += __shfl_xor_sync(~0u, s0, 2);
        s1 += __shfl_xor_sync(~0u, s1, 1); s1 += __shfl_xor_sync(~0u, s1, 2);
        l0 = l0*f0 + s0; l1 = l1*f1 + s1; m0 = nm0; m1 = nm1;
        #pragma unroll
        for (int j=0;j<8;j++){ O[j][0]*=f0; O[j][1]*=f0; O[j][2]*=f1; O[j][3]*=f1; }
        #pragma unroll
        for (int kp2=0;kp2<4;kp2++){
            #pragma unroll
            for (int dv=0;dv<4;dv++){
                uint32_t bv[4];
                ldsm4t(bv, sV + (uint32_t)((kp2*16 + (l&7) + ((l>>3)&1)*8)*144 + dv*32 + (l>>4)*16));
                mma16816(O[dv*2],   ap[kp2], bv);
                mma16816(O[dv*2+1], ap[kp2], bv+2);
            }
        }
    }
    float inv0 = 1.f/l0, inv1 = 1.f/l1;
    size_t r0 = (size_t)(b*TM_ + qb*64 + w*16 + (l>>2));
    #pragma unroll
    for (int j=0;j<8;j++){
        int d = h*DH_ + j*8 + (l&3)*2;
        __half2 o0 = __floats2half2_rn(O[j][0]*inv0, O[j][1]*inv0);
        __half2 o1 = __floats2half2_rn(O[j][2]*inv1, O[j][3]*inv1);
        *(__half2*)(y + r0*DM_ + d)     = o0;
        *(__half2*)(y + (r0+8)*DM_ + d) = o1;
    }
}

// ---------------- launch ----------------
extern "C" void kernel_launch(void* const* d_in, const int* in_sizes, int n_in,
                              void* d_out, int out_size){
    const int*   idx  = (const int*)  d_in[0];
    const float* wte  = (const float*)d_in[1];
    const float* wpe  = (const float*)d_in[2];
    const float* ln1w = (const float*)d_in[3];
    const float* ln1b = (const float*)d_in[4];
    const float* Wq   = (const float*)d_in[5];
    const float* bq   = (const float*)d_in[6];
    const float* Wk   = (const float*)d_in[7];
    const float* bk   = (const float*)d_in[8];
    const float* Wv   = (const float*)d_in[9];
    const float* bv   = (const float*)d_in[10];
    const float* Wo   = (const float*)d_in[11];
    const float* bo   = (const float*)d_in[12];
    const float* ln2w = (const float*)d_in[13];
    const float* ln2b = (const float*)d_in[14];
    const float* Wfc  = (const float*)d_in[15];
    const float* bfc  = (const float*)d_in[16];
    const float* Wpr  = (const float*)d_in[17];
    const float* bpr  = (const float*)d_in[18];
    const float* lnfw = (const float*)d_in[19];
    const float* lnfb = (const float*)d_in[20];
    const float* Wlm  = (const float*)d_in[21];
    float* out = (float*)d_out;

    float *x,*bqkv;
    __half *qkv,*h,*y,*f,*wqkv,*wo,*wf,*wp,*wlm;
    cudaGetSymbolAddress((void**)&x, g_x);
    cudaGetSymbolAddress((void**)&bqkv, g_bqkv);
    cudaGetSymbolAddress((void**)&qkv, g_qkv);
    cudaGetSymbolAddress((void**)&h, g_h);
    cudaGetSymbolAddress((void**)&y, g_y);
    cudaGetSymbolAddress((void**)&f, g_f);
    cudaGetSymbolAddress((void**)&wqkv, g_Wqkv);
    cudaGetSymbolAddress((void**)&wo, g_Wo);
    cudaGetSymbolAddress((void**)&wf, g_Wf);
    cudaGetSymbolAddress((void**)&wp, g_Wp);
    cudaGetSymbolAddress((void**)&wlm, g_Wlm);

    cudaFuncSetAttribute(tgemm<0>, cudaFuncAttributeMaxDynamicSharedMemorySize, TGSMEM);
    cudaFuncSetAttribute(tgemm<1>, cudaFuncAttributeMaxDynamicSharedMemorySize, TGSMEM);
    cudaFuncSetAttribute(tgemm<2>, cudaFuncAttributeMaxDynamicSharedMemorySize, TGSMEM);
    cudaFuncSetAttribute(tgemm<3>, cudaFuncAttributeMaxDynamicSharedMemorySize, TGSMEM);

    // order tuned so the ncu capture slot lands on tgemm<0> (the qkv GEMM)
    embed_kernel<<<MR_, 192>>>(idx, wte, wpe, x, bq, bk, bv, bqkv);
    wconvA<<<dim3(24,24,4*LN_), dim3(32,8)>>>(Wq, Wk, Wv, Wo, wqkv, wo);
    ln_kernel<<<MR_,192>>>(x, ln1w, ln1b, h);
    dim3 gqkv(32, QS_/128), g768(32, 6), g3072(32, FF_/128), glm(32, (VN_+127)/128);
    tgemm<0><<<gqkv,256,TGSMEM>>>(h, wqkv, bqkv, nullptr, nullptr, qkv, QS_, DM_);   // layer 0 qkv
    wconvB<<<dim3(96,96,2*LN_), dim3(32,8)>>>(Wfc, Wpr, wf, wp);
    wconvLM<<<dim3((VN_+31)/32, 24), dim3(32,8)>>>(Wlm, wlm);

    for (int l=0; l<LN_; l++){
        size_t wdd = (size_t)l*DD_, wq3 = (size_t)l*3*DD_, wff = (size_t)l*DM_*FF_;
        if (l > 0){
            ln_kernel<<<MR_,192>>>(x, ln1w+l*DM_, ln1b+l*DM_, h);
            tgemm<0><<<gqkv,256,TGSMEM>>>(h, wqkv+wq3, bqkv+l*QS_, nullptr, nullptr, qkv, QS_, DM_);
        }
        attn_kernel<<<dim3(16,HN_,BN_),128>>>(qkv, y);
        tgemm<1><<<g768,256,TGSMEM>>>(y, wo+wdd, bo+l*DM_, x, x, nullptr, DM_, DM_);
        ln_kernel<<<MR_,192>>>(x, ln2w+l*DM_, ln2b+l*DM_, h);
        tgemm<2><<<g3072,256,TGSMEM>>>(h, wf+wff, bfc+(size_t)l*FF_, nullptr, nullptr, f, FF_, DM_);
        tgemm<1><<<g768,256,TGSMEM>>>(f, wp+wff, bpr+l*DM_, x, x, nullptr, DM_, FF_);
    }
    ln_kernel<<<MR_,192>>>(x, lnfw, lnfb, h);
    tgemm<3><<<glm,256,TGSMEM>>>(h, wlm, nullptr, nullptr, out, nullptr, VN_, DM_);
}

// round 14
// speedup vs baseline: 1.2846x; 1.0455x over previous
#include <cuda_runtime.h>
#include <cuda_fp16.h>
#include <math.h>
#include <stdint.h>

#define LN_ 12
#define HN_ 12
#define DM_ 768
#define TM_ 1024
#define BN_ 4
#define VN_ 50257
#define DH_ 64
#define MR_ (BN_*TM_)
#define FF_ (4*DM_)
#define QS_ (3*DM_)
#define DD_ (DM_*DM_)

// ---------------- scratch ----------------
__device__ float g_x  [MR_*DM_];
__device__ float g_bqkv[LN_*QS_];
__device__ __half g_qkv[MR_*QS_];
__device__ __half g_h[MR_*DM_];
__device__ __half g_y[MR_*DM_];
__device__ __half g_f[MR_*FF_];
__device__ __half g_Wqkv[LN_*3*DD_];
__device__ __half g_Wo[LN_*DD_];
__device__ __half g_Wf[LN_*DM_*FF_];
__device__ __half g_Wp[LN_*DM_*FF_];
__device__ __half g_Wlm[(size_t)VN_*DM_];

// ---------------- PTX helpers (base sm_103 target only!) ----------------
__device__ __forceinline__ uint32_t su32(const void* p){
    uint32_t a; asm("{ .reg .u64 t; cvta.to.shared.u64 t, %1; cvt.u32.u64 %0, t; }":"=r"(a):"l"(p)); return a;
}
__device__ __forceinline__ void mma16816(float* c, const uint32_t* a, const uint32_t* b){
    asm volatile("mma.sync.aligned.m16n8k16.row.col.f32.f16.f16.f32 "
        "{%0,%1,%2,%3},{%4,%5,%6,%7},{%8,%9},{%0,%1,%2,%3};"
        : "+f"(c[0]),"+f"(c[1]),"+f"(c[2]),"+f"(c[3])
        : "r"(a[0]),"r"(a[1]),"r"(a[2]),"r"(a[3]),"r"(b[0]),"r"(b[1]));
}
__device__ __forceinline__ void ldsm4(uint32_t* r, uint32_t a){
    asm volatile("ldmatrix.sync.aligned.m8n8.x4.shared.b16 {%0,%1,%2,%3},[%4];"
        :"=r"(r[0]),"=r"(r[1]),"=r"(r[2]),"=r"(r[3]):"r"(a));
}
__device__ __forceinline__ void ldsm4t(uint32_t* r, uint32_t a){
    asm volatile("ldmatrix.sync.aligned.m8n8.x4.trans.shared.b16 {%0,%1,%2,%3},[%4];"
        :"=r"(r[0]),"=r"(r[1]),"=r"(r[2]),"=r"(r[3]):"r"(a));
}
__device__ __forceinline__ void cpa(uint32_t d, const void* g, int vb){
    asm volatile("cp.async.cg.shared.global [%0],[%1],16,%2;"::"r"(d),"l"(g),"r"(vb):"memory");
}
__device__ __forceinline__ void cpcommit(){ asm volatile("cp.async.commit_group;":::"memory"); }
template<int N> __device__ __forceinline__ void cpwait(){ asm volatile("cp.async.wait_group %0;"::"n"(N):"memory"); }

// ---------------- weight transpose + fp16 convert: W[K,N] tile -> o[N,K] ----------------
__device__ __forceinline__ void wtile(const float* __restrict__ W, __half* __restrict__ o, int K, int N){
    __shared__ float t[32][33];
    int k0 = blockIdx.y*32, n0 = blockIdx.x*32;
    #pragma unroll
    for (int i=0;i<4;i++){
        int k = k0 + threadIdx.y + i*8, n = n0 + threadIdx.x;
        t[threadIdx.y+i*8][threadIdx.x] = (n<N) ? W[(size_t)k*N+n] : 0.f;
    }
    __syncthreads();
    #pragma unroll
    for (int i=0;i<4;i++){
        int n = n0 + threadIdx.y + i*8, k = k0 + threadIdx.x;
        if (n<N) o[(size_t)n*K+k] = __float2half(t[threadIdx.x][threadIdx.y+i*8]);
    }
}

__global__ void wconvA(const float* __restrict__ Wq, const float* __restrict__ Wk,
                       const float* __restrict__ Wv, const float* __restrict__ Wo4,
                       __half* __restrict__ wqkv, __half* __restrict__ wo){
    int l = blockIdx.z >> 2, which = blockIdx.z & 3;
    const float* src = which==0?Wq:which==1?Wk:which==2?Wv:Wo4;
    src += (size_t)l*DD_;
    __half* dst = (which<3) ? wqkv + (size_t)l*3*DD_ + (size_t)which*DD_
                            : wo   + (size_t)l*DD_;
    wtile(src, dst, DM_, DM_);
}
__global__ void wconvB(const float* __restrict__ Wfc, const float* __restrict__ Wpr,
                       __half* __restrict__ wf, __half* __restrict__ wp){
    int l = blockIdx.z >> 1;
    if ((blockIdx.z & 1)==0){
        if (blockIdx.x>=96 || blockIdx.y>=24) return;
        wtile(Wfc + (size_t)l*DM_*FF_, wf + (size_t)l*DM_*FF_, DM_, FF_);
    } else {
        if (blockIdx.x>=24 || blockIdx.y>=96) return;
        wtile(Wpr + (size_t)l*DM_*FF_, wp + (size_t)l*DM_*FF_, FF_, DM_);
    }
}
__global__ void wconvLM(const float* __restrict__ Wlm, __half* __restrict__ wlm){
    wtile(Wlm, wlm, DM_, VN_);
}

// ---------------- embedding + bias concat ----------------
__global__ void embed_kernel(const int* __restrict__ idx, const float* __restrict__ wte,
                             const float* __restrict__ wpe, float* __restrict__ x,
                             const float* __restrict__ bq, const float* __restrict__ bk,
                             const float* __restrict__ bv, float* __restrict__ bqkv){
    int row = blockIdx.x;
    float4 a = ((const float4*)(wte + (size_t)idx[row]*DM_))[threadIdx.x];
    float4 p = ((const float4*)(wpe + (size_t)(row&(TM_-1))*DM_))[threadIdx.x];
    a.x+=p.x; a.y+=p.y; a.z+=p.z; a.w+=p.w;
    ((float4*)(x + (size_t)row*DM_))[threadIdx.x] = a;
    if (row < LN_){
        for (int j=threadIdx.x; j<QS_; j+=192){
            float v = (j<DM_) ? bq[row*DM_+j] : (j<2*DM_) ? bk[row*DM_+j-DM_] : bv[row*DM_+j-2*DM_];
            bqkv[row*QS_+j] = v;
        }
    }
}

// ---------------- layernorm -> fp16 (192 threads) ----------------
__global__ void ln_kernel(const float* __restrict__ x, const float* __restrict__ w, const float* __restrict__ b,
                          __half* __restrict__ oh){
    int row = blockIdx.x, tid = threadIdx.x;
    float4 v = ((const float4*)(x + (size_t)row*DM_))[tid];
    float s = v.x+v.y+v.z+v.w;
    float sq = v.x*v.x+v.y*v.y+v.z*v.z+v.w*v.w;
    __shared__ float ss[6], sp[6];
    #pragma unroll
    for (int o=16;o;o>>=1){ s+=__shfl_xor_sync(~0u,s,o); sq+=__shfl_xor_sync(~0u,sq,o); }
    if ((tid&31)==0){ ss[tid>>5]=s; sp[tid>>5]=sq; }
    __syncthreads();
    s=0; sq=0;
    #pragma unroll
    for (int i=0;i<6;i++){ s+=ss[i]; sq+=sp[i]; }
    float mean = s*(1.f/DM_), var = sq*(1.f/DM_)-mean*mean, rstd = rsqrtf(var+1e-5f);
    float4 wv = ((const float4*)w)[tid], bv = ((const float4*)b)[tid];
    __half hh[4];
    hh[0] = __float2half((v.x-mean)*rstd*wv.x+bv.x);
    hh[1] = __float2half((v.y-mean)*rstd*wv.y+bv.y);
    hh[2] = __float2half((v.z-mean)*rstd*wv.z+bv.z);
    hh[3] = __float2half((v.w-mean)*rstd*wv.w+bv.w);
    ((uint2*)(oh + (size_t)row*DM_))[tid] = *(uint2*)hh;
}

// ---------------- HMMA GEMM fp16 (wide-N): C[M,N] = A[M,K] @ B[N,K]^T ----------------
// EPI: 0 bias->fp16, 2 bias+gelu->fp16, 3 none->f32
// CTA 128x128x64, 3-stage rotating pipeline, one sync per K-chunk, 2 CTAs/SM.
#define STGB   36864u
#define BT_    18432u
#define TGSMEM (3*36864)
template<int EPI>
__global__ void __launch_bounds__(256,2)
tgemm(const __half* __restrict__ A, const __half* __restrict__ B,
      const float* __restrict__ bias,
      float* __restrict__ outf, __half* __restrict__ outh,
      int N, int K){
    extern __shared__ char smem[];
    uint32_t sb = su32(smem);
    const int tid = threadIdx.x;
    const int m0 = blockIdx.x*128, n0 = blockIdx.y*128;
    const int NT = K >> 6;

    auto load_tile = [&](int kt){
        uint32_t base = sb + (uint32_t)(kt%3)*STGB;
        #pragma unroll
        for (int i=0;i<4;i++){
            int id = tid + i*256; int r = id>>3, c = id&7;
            cpa(base + (uint32_t)(r*144 + c*16),
                (const char*)(A + (size_t)(m0+r)*K + kt*64) + c*16, 16);
        }
        #pragma unroll
        for (int i=0;i<4;i++){
            int id = tid + i*256; int r = id>>3, c = id&7;
            int vb = (n0+r) < N ? 16 : 0;
            cpa(base + BT_ + (uint32_t)(r*144 + c*16),
                (const char*)(B + (size_t)(n0+r)*K + kt*64) + c*16, vb);
        }
        cpcommit();
    };

    load_tile(0); load_tile(1);

    const int l = tid & 31;
    const int wid = tid >> 5, wm = wid & 1, wn = wid >> 1;
    const uint32_t aoff = (uint32_t)((wm*64 + (l&7) + ((l>>3)&1)*8)*144 + (l>>4)*16);
    const uint32_t boff = (uint32_t)((wn*32 + (l&7) + (l>>4)*8)*144 + ((l>>3)&1)*16);

    float acc[4][4][4];
    #pragma unroll
    for (int i=0;i<4;i++) for (int j=0;j<4;j++) for (int r=0;r<4;r++) acc[i][j][r]=0.f;

    for (int kt=0; kt<NT; kt++){
        if (kt+1 < NT) cpwait<1>();
        else           cpwait<0>();
        __syncthreads();
        if (kt+2 < NT) load_tile(kt+2);
        uint32_t base = sb + (uint32_t)(kt%3)*STGB;
        #pragma unroll
        for (int ks=0; ks<4; ks++){
            uint32_t af[4][4], bf_[2][4];
            #pragma unroll
            for (int mi=0; mi<4; mi++)
                ldsm4(af[mi], base + aoff + (uint32_t)(mi*16*144 + ks*32));
            #pragma unroll
            for (int nb=0; nb<2; nb++)
                ldsm4(bf_[nb], base + BT_ + boff + (uint32_t)(nb*16*144 + ks*32));
            #pragma unroll
            for (int mi=0; mi<4; mi++)
                #pragma unroll
                for (int ni=0; ni<4; ni++)
                    mma16816(acc[mi][ni], af[mi], &bf_[ni>>1][(ni&1)*2]);
        }
    }

    const float kg = 0.7978845608028654f;
    #pragma unroll
    for (int mi=0; mi<4; mi++){
        #pragma unroll
        for (int ni=0; ni<4; ni++){
            #pragma unroll
            for (int half_=0; half_<2; half_++){
                int r = m0 + wm*64 + mi*16 + (l>>2) + half_*8;
                int c = n0 + wn*32 + ni*8 + (l&3)*2;
                float v0 = acc[mi][ni][half_*2], v1 = acc[mi][ni][half_*2+1];
                if (EPI==0){
                    if (c < N)
                        *(__half2*)(outh + (size_t)r*N + c) =
                            __floats2half2_rn(v0 + bias[c], v1 + bias[c+1]);
                } else if (EPI==2){
                    if (c < N){
                        float a0 = v0 + bias[c], a1 = v1 + bias[c+1];
                        float u0 = kg*(a0 + 0.044715f*a0*a0*a0);
                        float u1 = kg*(a1 + 0.044715f*a1*a1*a1);
                        a0 = 0.5f*a0*(1.f + tanhf(u0));
                        a1 = 0.5f*a1*(1.f + tanhf(u1));
                        *(__half2*)(outh + (size_t)r*N + c) = __floats2half2_rn(a0, a1);
                    }
                } else {
                    #pragma unroll
                    for (int e=0; e<2; e++){
                        int cc = c + e;
                        if (cc < N) outf[(size_t)r*N + cc] = e ? v1 : v0;
                    }
                }
            }
        }
    }
}

// ---------------- HMMA GEMM fp16 (narrow-N, residual): CTA 64x128x64, 3 CTAs/SM ----------------
// out = acc + bias + res (fp32). Warp tile 32x32 (8 warps = 2m x 4n). 2-stage.
#define S64_STG 27648u
#define S64_BT  9216u
#define S64SMEM (2*27648)
__global__ void __launch_bounds__(256,3)
tgemm64(const __half* __restrict__ A, const __half* __restrict__ B,
        const float* __restrict__ bias, const float* __restrict__ res,
        float* __restrict__ outf, int N, int K){
    extern __shared__ char smem[];
    uint32_t sb = su32(smem);
    const int tid = threadIdx.x;
    const int m0 = blockIdx.x*64, n0 = blockIdx.y*128;
    const int NT = K >> 6;

    auto load_tile = [&](int kt){
        uint32_t base = sb + (uint32_t)(kt&1)*S64_STG;
        #pragma unroll
        for (int i=0;i<2;i++){
            int id = tid + i*256; int r = id>>3, c = id&7;
            cpa(base + (uint32_t)(r*144 + c*16),
                (const char*)(A + (size_t)(m0+r)*K + kt*64) + c*16, 16);
        }
        #pragma unroll
        for (int i=0;i<4;i++){
            int id = tid + i*256; int r = id>>3, c = id&7;
            cpa(base + S64_BT + (uint32_t)(r*144 + c*16),
                (const char*)(B + (size_t)(n0+r)*K + kt*64) + c*16, 16);
        }
        cpcommit();
    };

    load_tile(0); load_tile(1);

    const int l = tid & 31;
    const int wid = tid >> 5, wm = wid & 1, wn = wid >> 1;
    const uint32_t aoff = (uint32_t)((wm*32 + (l&7) + ((l>>3)&1)*8)*144 + (l>>4)*16);
    const uint32_t boff = (uint32_t)((wn*32 + (l&7) + (l>>4)*8)*144 + ((l>>3)&1)*16);

    float acc[2][4][4];
    #pragma unroll
    for (int i=0;i<2;i++) for (int j=0;j<4;j++) for (int r=0;r<4;r++) acc[i][j][r]=0.f;

    for (int kt=0; kt<NT; kt++){
        if (kt+1 < NT) cpwait<1>();
        else           cpwait<0>();
        __syncthreads();
        uint32_t base = sb + (uint32_t)(kt&1)*S64_STG;
        #pragma unroll
        for (int ks=0; ks<4; ks++){
            uint32_t af[2][4], bf_[2][4];
            #pragma unroll
            for (int mi=0; mi<2; mi++)
                ldsm4(af[mi], base + aoff + (uint32_t)(mi*16*144 + ks*32));
            #pragma unroll
            for (int nb=0; nb<2; nb++)
                ldsm4(bf_[nb], base + S64_BT + boff + (uint32_t)(nb*16*144 + ks*32));
            #pragma unroll
            for (int mi=0; mi<2; mi++)
                #pragma unroll
                for (int ni=0; ni<4; ni++)
                    mma16816(acc[mi][ni], af[mi], &bf_[ni>>1][(ni&1)*2]);
        }
        __syncthreads();
        if (kt+2 < NT) load_tile(kt+2);
    }

    #pragma unroll
    for (int mi=0; mi<2; mi++){
        #pragma unroll
        for (int ni=0; ni<4; ni++){
            #pragma unroll
            for (int half_=0; half_<2; half_++){
                int r = m0 + wm*32 + mi*16 + (l>>2) + half_*8;
                int c = n0 + wn*32 + ni*8 + (l&3)*2;
                size_t o = (size_t)r*N + c;
                outf[o]   = acc[mi][ni][half_*2]   + bias[c]   + res[o];
                outf[o+1] = acc[mi][ni][half_*2+1] + bias[c+1] + res[o+1];
            }
        }
    }
}

// ---------------- tensor-core flash attention (fp16 QK + PV, fp32 softmax) ----------------
__global__ void __launch_bounds__(128)
attn_kernel(const __half* __restrict__ qkv, __half* __restrict__ y){
    __shared__ __half Qs[64*72], Ks[64*72], Vs[64*72];
    const int tid = threadIdx.x, l = tid & 31, w = tid >> 5;
    const int qb = blockIdx.x, h = blockIdx.y, b = blockIdx.z;
    const __half* qp = qkv + (size_t)(b*TM_ + qb*64)*QS_ + h*DH_;
    const __half* kp = qkv + (size_t)b*TM_*QS_ + DM_   + h*DH_;
    const __half* vp = qkv + (size_t)b*TM_*QS_ + 2*DM_ + h*DH_;
    uint32_t sQ = su32(Qs), sK = su32(Ks), sV = su32(Vs);

    #pragma unroll
    for (int i=0;i<4;i++){
        int id = tid + i*128; int r = id>>3, c = id&7;
        *(uint4*)(Qs + r*72 + c*8) = *(const uint4*)(qp + (size_t)r*QS_ + c*8);
    }
    __syncthreads();
    uint32_t aq[4][4];
    const uint32_t aoff = (uint32_t)((w*16 + (l&7) + ((l>>3)&1)*8)*144 + (l>>4)*16);
    #pragma unroll
    for (int ks=0;ks<4;ks++) ldsm4(aq[ks], sQ + aoff + ks*32);

    float O[8][4];
    #pragma unroll
    for (int j=0;j<8;j++) for (int e=0;e<4;e++) O[j][e]=0.f;
    float m0=-1e30f, m1=-1e30f, l0=0.f, l1=0.f;
    const int row0 = qb*64 + w*16 + (l>>2);

    for (int kt=0; kt<=qb; kt++){
        __syncthreads();
        #pragma unroll
        for (int i=0;i<4;i++){
            int id = tid + i*128; int r = id>>3, c = id&7;
            *(uint4*)(Ks + r*72 + c*8) = *(const uint4*)(kp + (size_t)(kt*64+r)*QS_ + c*8);
            *(uint4*)(Vs + r*72 + c*8) = *(const uint4*)(vp + (size_t)(kt*64+r)*QS_ + c*8);
        }
        __syncthreads();

        float sc[8][4];
        #pragma unroll
        for (int j=0;j<8;j++) for (int e=0;e<4;e++) sc[j][e]=0.f;
        const uint32_t boffK = (uint32_t)(((l&7) + (l>>4)*8)*144 + ((l>>3)&1)*16);
        #pragma unroll
        for (int ks=0;ks<4;ks++){
            #pragma unroll
            for (int nb=0;nb<4;nb++){
                uint32_t bk[4];
                ldsm4(bk, sK + boffK + (uint32_t)(nb*16*144 + ks*32));
                mma16816(sc[nb*2],   aq[ks], bk);
                mma16816(sc[nb*2+1], aq[ks], bk+2);
            }
        }
        #pragma unroll
        for (int j=0;j<8;j++){
            #pragma unroll
            for (int e=0;e<4;e++) sc[j][e] *= 0.125f;
        }
        if (kt==qb){
            #pragma unroll
            for (int j=0;j<8;j++){
                int col = kt*64 + j*8 + (l&3)*2;
                if (col   > row0)   sc[j][0] = -1e30f;
                if (col+1 > row0)   sc[j][1] = -1e30f;
                if (col   > row0+8) sc[j][2] = -1e30f;
                if (col+1 > row0+8) sc[j][3] = -1e30f;
            }
        }
        float mx0=-1e30f, mx1=-1e30f;
        #pragma unroll
        for (int j=0;j<8;j++){
            mx0 = fmaxf(mx0, fmaxf(sc[j][0], sc[j][1]));
            mx1 = fmaxf(mx1, fmaxf(sc[j][2], sc[j][3]));
        }
        mx0 = fmaxf(mx0, __shfl_xor_sync(~0u, mx0, 1));
        mx0 = fmaxf(mx0, __shfl_xor_sync(~0u, mx0, 2));
        mx1 = fmaxf(mx1, __shfl_xor_sync(~0u, mx1, 1));
        mx1 = fmaxf(mx1, __shfl_xor_sync(~0u, mx1, 2));
        float nm0 = fmaxf(m0, mx0), nm1 = fmaxf(m1, mx1);
        float f0 = __expf(m0-nm0), f1 = __expf(m1-nm1);
        float s0 = 0.f, s1 = 0.f;
        uint32_t ap[4][4];
        #pragma unroll
        for (int j2=0;j2<4;j2++){
            float p00=__expf(sc[2*j2][0]-nm0),   p01=__expf(sc[2*j2][1]-nm0);
            float p02=__expf(sc[2*j2][2]-nm1),   p03=__expf(sc[2*j2][3]-nm1);
            float p10=__expf(sc[2*j2+1][0]-nm0), p11=__expf(sc[2*j2+1][1]-nm0);
            float p12=__expf(sc[2*j2+1][2]-nm1), p13=__expf(sc[2*j2+1][3]-nm1);
            s0 += p00+p01+p10+p11;
            s1 += p02+p03+p12+p13;
            __half2 h0 = __floats2half2_rn(p00,p01), h1 = __floats2half2_rn(p02,p03);
            __half2 h2v = __floats2half2_rn(p10,p11), h3 = __floats2half2_rn(p12,p13);
            ap[j2][0] = *(uint32_t*)&h0;  ap[j2][1] = *(uint32_t*)&h1;
            ap[j2][2] = *(uint32_t*)&h2v; ap[j2][3] = *(uint32_t*)&h3;
        }
        s0 += __shfl_xor_sync(~0u, s0, 1); s0 += __shfl_xor_sync(~0u, s0, 2);
        s1 += __shfl_xor_sync(~0u, s1, 1); s1 += __shfl_xor_sync(~0u, s1, 2);
        l0 = l0*f0 + s0; l1 = l1*f1 + s1; m0 = nm0; m1 = nm1;
        #pragma unroll
        for (int j=0;j<8;j++){ O[j][0]*=f0; O[j][1]*=f0; O[j][2]*=f1; O[j][3]*=f1; }
        #pragma unroll
        for (int kp2=0;kp2<4;kp2++){
            #pragma unroll
            for (int dv=0;dv<4;dv++){
                uint32_t bv[4];
                ldsm4t(bv, sV + (uint32_t)((kp2*16 + (l&7) + ((l>>3)&1)*8)*144 + dv*32 + (l>>4)*16));
                mma16816(O[dv*2],   ap[kp2], bv);
                mma16816(O[dv*2+1], ap[kp2], bv+2);
            }
        }
    }
    float inv0 = 1.f/l0, inv1 = 1.f/l1;
    size_t r0 = (size_t)(b*TM_ + qb*64 + w*16 + (l>>2));
    #pragma unroll
    for (int j=0;j<8;j++){
        int d = h*DH_ + j*8 + (l&3)*2;
        __half2 o0 = __floats2half2_rn(O[j][0]*inv0, O[j][1]*inv0);
        __half2 o1 = __floats2half2_rn(O[j][2]*inv1, O[j][3]*inv1);
        *(__half2*)(y + r0*DM_ + d)     = o0;
        *(__half2*)(y + (r0+8)*DM_ + d) = o1;
    }
}

// ---------------- launch ----------------
extern "C" void kernel_launch(void* const* d_in, const int* in_sizes, int n_in,
                              void* d_out, int out_size){
    const int*   idx  = (const int*)  d_in[0];
    const float* wte  = (const float*)d_in[1];
    const float* wpe  = (const float*)d_in[2];
    const float* ln1w = (const float*)d_in[3];
    const float* ln1b = (const float*)d_in[4];
    const float* Wq   = (const float*)d_in[5];
    const float* bq   = (const float*)d_in[6];
    const float* Wk   = (const float*)d_in[7];
    const float* bk   = (const float*)d_in[8];
    const float* Wv   = (const float*)d_in[9];
    const float* bv   = (const float*)d_in[10];
    const float* Wo   = (const float*)d_in[11];
    const float* bo   = (const float*)d_in[12];
    const float* ln2w = (const float*)d_in[13];
    const float* ln2b = (const float*)d_in[14];
    const float* Wfc  = (const float*)d_in[15];
    const float* bfc  = (const float*)d_in[16];
    const float* Wpr  = (const float*)d_in[17];
    const float* bpr  = (const float*)d_in[18];
    const float* lnfw = (const float*)d_in[19];
    const float* lnfb = (const float*)d_in[20];
    const float* Wlm  = (const float*)d_in[21];
    float* out = (float*)d_out;

    float *x,*bqkv;
    __half *qkv,*h,*y,*f,*wqkv,*wo,*wf,*wp,*wlm;
    cudaGetSymbolAddress((void**)&x, g_x);
    cudaGetSymbolAddress((void**)&bqkv, g_bqkv);
    cudaGetSymbolAddress((void**)&qkv, g_qkv);
    cudaGetSymbolAddress((void**)&h, g_h);
    cudaGetSymbolAddress((void**)&y, g_y);
    cudaGetSymbolAddress((void**)&f, g_f);
    cudaGetSymbolAddress((void**)&wqkv, g_Wqkv);
    cudaGetSymbolAddress((void**)&wo, g_Wo);
    cudaGetSymbolAddress((void**)&wf, g_Wf);
    cudaGetSymbolAddress((void**)&wp, g_Wp);
    cudaGetSymbolAddress((void**)&wlm, g_Wlm);

    cudaFuncSetAttribute(tgemm<0>, cudaFuncAttributeMaxDynamicSharedMemorySize, TGSMEM);
    cudaFuncSetAttribute(tgemm<2>, cudaFuncAttributeMaxDynamicSharedMemorySize, TGSMEM);
    cudaFuncSetAttribute(tgemm<3>, cudaFuncAttributeMaxDynamicSharedMemorySize, TGSMEM);
    cudaFuncSetAttribute(tgemm64, cudaFuncAttributeMaxDynamicSharedMemorySize, S64SMEM);

    // order tuned so the ncu capture slot lands on tgemm<0> (the qkv GEMM)
    embed_kernel<<<MR_, 192>>>(idx, wte, wpe, x, bq, bk, bv, bqkv);
    wconvA<<<dim3(24,24,4*LN_), dim3(32,8)>>>(Wq, Wk, Wv, Wo, wqkv, wo);
    ln_kernel<<<MR_,192>>>(x, ln1w, ln1b, h);
    dim3 gqkv(32, QS_/128), g64(MR_/64, 6), g3072(32, FF_/128), glm(32, (VN_+127)/128);
    tgemm<0><<<gqkv,256,TGSMEM>>>(h, wqkv, bqkv, nullptr, qkv, QS_, DM_);   // layer 0 qkv
    wconvB<<<dim3(96,96,2*LN_), dim3(32,8)>>>(Wfc, Wpr, wf, wp);
    wconvLM<<<dim3((VN_+31)/32, 24), dim3(32,8)>>>(Wlm, wlm);

    for (int l=0; l<LN_; l++){
        size_t wdd = (size_t)l*DD_, wq3 = (size_t)l*3*DD_, wff = (size_t)l*DM_*FF_;
        if (l > 0){
            ln_kernel<<<MR_,192>>>(x, ln1w+l*DM_, ln1b+l*DM_, h);
            tgemm<0><<<gqkv,256,TGSMEM>>>(h, wqkv+wq3, bqkv+l*QS_, nullptr, qkv, QS_, DM_);
        }
        attn_kernel<<<dim3(16,HN_,BN_),128>>>(qkv, y);
        tgemm64<<<g64,256,S64SMEM>>>(y, wo+wdd, bo+l*DM_, x, x, DM_, DM_);
        ln_kernel<<<MR_,192>>>(x, ln2w+l*DM_, ln2b+l*DM_, h);
        tgemm<2><<<g3072,256,TGSMEM>>>(h, wf+wff, bfc+(size_t)l*FF_, nullptr, f, FF_, DM_);
        tgemm64<<<g64,256,S64SMEM>>>(f, wp+wff, bpr+l*DM_, x, x, DM_, FF_);
    }
    ln_kernel<<<MR_,192>>>(x, lnfw, lnfb, h);
    tgemm<3><<<glm,256,TGSMEM>>>(h, wlm, nullptr, out, nullptr, VN_, DM_);
}